// round 13
// baseline (speedup 1.0000x reference)
#include <cuda_runtime.h>
#include <cuda_bf16.h>
#include <cuda_fp16.h>
#include <math_constants.h>
#include <cub/cub.cuh>
#include <cstdint>

// ---------------------------------------------------------------------------
// Problem constants
// ---------------------------------------------------------------------------
#define HH 64
#define WWID 64
#define CIN 512
#define NB 2
#define NANCH 9
#define ATOT (HH*WWID*NANCH)      // 36864
#define NPRE 6000
#define NPOST 300
#define MASKW 94                  // ceil(6000/64)
#define NMS_T 0.7f

#define MTOT (NB*HH*WWID)         // 8192 pixel rows
#define KTAP 9

// Output layout (float32, concatenated in reference return order)
#define OFF_LOCS   0
#define OFF_SCORES (NB*ATOT*4)
#define OFF_ROIS   (OFF_SCORES + NB*ATOT*2)
#define OFF_RIDX   (OFF_ROIS + NB*NPOST*4)
#define OFF_ANCHOR (OFF_RIDX + NB*NPOST)
#define OFF_VMASK  (OFF_ANCHOR + ATOT*4)

#define APLSZ ((size_t)MTOT*CIN)        // elements per A fp16 plane
#define BPLSZ ((size_t)KTAP*CIN*CIN)    // elements per B fp16 plane
#define BSCALE 64.0f
#define BUNSCALE 0.015625f
#define NQ 4                             // heads channel-split = conv N-tiles

// ---------------------------------------------------------------------------
// Scratch
// ---------------------------------------------------------------------------
__device__ __half g_axh[2*APLSZ];                // input fp16 planes (NHWC)
__device__ __half g_bxh[2*BPLSZ];                // weight planes [tap][k][c], x64
__device__ float g_part[(size_t)NQ*NB*56*4096]; // heads partials [q][n][o][pix]
__device__ float g_score[NB*ATOT];
__device__ uint32_t g_key32[NB*ATOT];
__device__ uint32_t g_key32_out[NB*ATOT];
__device__ int   g_val[NB*ATOT];
__device__ int   g_val_out[NB*ATOT];
__device__ float4 g_roi[NB*ATOT];
__device__ float4 g_boxes[NB*NPRE];
__device__ float g_boxsc[NB*NPRE];
__device__ unsigned long long g_mask[(size_t)NB*NPRE*MASKW];
__device__ int g_kept[NB*NPOST];
__device__ __align__(256) unsigned char g_cub_temp[8<<20];

// ---------------------------------------------------------------------------
// PTX helpers
// ---------------------------------------------------------------------------
__device__ __forceinline__ uint32_t smem_u32(const void* p) {
    uint32_t a;
    asm("{ .reg .u64 t; cvta.to.shared.u64 t, %1; cvt.u32.u64 %0, t; }" : "=r"(a) : "l"(p));
    return a;
}
__device__ __forceinline__ void cp16(uint32_t dst, const void* src, int srcsize) {
    asm volatile("cp.async.cg.shared.global [%0], [%1], 16, %2;"
                 :: "r"(dst), "l"(src), "r"(srcsize) : "memory");
}
__device__ __forceinline__ void cp_commit() { asm volatile("cp.async.commit_group;" ::: "memory"); }
template<int N> __device__ __forceinline__ void cp_wait() {
    asm volatile("cp.async.wait_group %0;" :: "n"(N) : "memory");
}

#define LDSM4(r0, r1, r2, r3, a) \
    asm volatile("ldmatrix.sync.aligned.m8n8.x4.shared.b16 {%0,%1,%2,%3}, [%4];" \
                 : "=r"(r0), "=r"(r1), "=r"(r2), "=r"(r3) : "r"(a))

// fp16 2-way split
__device__ __forceinline__ void f16split(float v, __half& o0, __half& o1) {
    __half h0 = __float2half_rn(v);
    float r = v - __half2float(h0);
    o0 = h0;
    o1 = __float2half_rn(r);
}

#define MMA_F16(d, a, b) \
    asm volatile("mma.sync.aligned.m16n8k16.row.col.f32.f16.f16.f32 " \
                 "{%0,%1,%2,%3},{%4,%5,%6,%7},{%8,%9},{%0,%1,%2,%3};" \
                 : "+f"((d)[0]), "+f"((d)[1]), "+f"((d)[2]), "+f"((d)[3]) \
                 : "r"((a)[0]), "r"((a)[1]), "r"((a)[2]), "r"((a)[3]), \
                   "r"((b)[0]), "r"((b)[1]))

#define MMA_F16_ZC(d, a, b, z) \
    asm volatile("mma.sync.aligned.m16n8k16.row.col.f32.f16.f16.f32 " \
                 "{%0,%1,%2,%3},{%4,%5,%6,%7},{%8,%9},{%10,%10,%10,%10};" \
                 : "=f"((d)[0]), "=f"((d)[1]), "=f"((d)[2]), "=f"((d)[3]) \
                 : "r"((a)[0]), "r"((a)[1]), "r"((a)[2]), "r"((a)[3]), \
                   "r"((b)[0]), "r"((b)[1]), "f"(z))

// ---------------------------------------------------------------------------
// No-op kernels: position mma_conv_kernel as launch #4 for ncu capture
// ---------------------------------------------------------------------------
__global__ void noop_kernel() {}

// ---------------------------------------------------------------------------
// Combined input/weight split. grid (128, 16, 3).
// ---------------------------------------------------------------------------
__global__ void split_kernel(const float* __restrict__ x, const float* __restrict__ w) {
    if (blockIdx.z < 2) {
        __shared__ float tile[32][33];
        int pt = blockIdx.x, ct = blockIdx.y, n = blockIdx.z;
        int tx = threadIdx.x & 31, ty = threadIdx.x >> 5;
#pragma unroll
        for (int r = 0; r < 4; r++) {
            int c = ct*32 + ty + r*8;
            int p = pt*32 + tx;
            tile[ty + r*8][tx] = x[((size_t)(n*CIN + c))*4096 + p];
        }
        __syncthreads();
        int cl = (threadIdx.x & 15)*2;
        int pl0 = threadIdx.x >> 4;
#pragma unroll
        for (int r = 0; r < 2; r++) {
            int pl = pl0 + r*16;
            int pg = pt*32 + pl;
            int cg = ct*32 + cl;
            float a0 = tile[cl][pl];
            float a1 = tile[cl+1][pl];
            __half h00, h01, h10, h11;
            f16split(a0, h00, h01);
            f16split(a1, h10, h11);
            size_t o = ((size_t)(n*4096 + pg))*CIN + cg;
            *(__half2*)&g_axh[o] = __halves2half2(h00, h10);
            *(__half2*)&g_axh[APLSZ + o] = __halves2half2(h01, h11);
        }
    } else {
        int base = (blockIdx.y*128 + blockIdx.x)*256 + threadIdx.x;
        for (int e = base; e < KTAP*CIN*CIN; e += 128*16*256) {
            int c = e & 511;
            int k = (e >> 9) & 511;
            int tap = e >> 18;
            float v = w[((size_t)k*CIN + c)*KTAP + tap] * BSCALE;
            __half h0, h1;
            f16split(v, h0, h1);
            g_bxh[e] = h0;
            g_bxh[BPLSZ + e] = h1;
        }
    }
}

// ---------------------------------------------------------------------------
// fp16x3 emulated-fp32 conv GEMM, cin-major / tap-minor (A-band reuse).
// ---------------------------------------------------------------------------
#define A_PLANE 21120
#define A_BUF   42240
#define B_BASE  84480
#define B_SLOT  20480
#define B_PLANE 10240
#define SMEM_DYN 145920
#define HSTRIDE 132

__device__ __forceinline__ void load_a(int cc, int parity, uint32_t sb,
                                       int n, int y0, int tid) {
    int c0 = cc*32;
    for (int e = tid; e < 2112; e += 256) {
        int seg = e & 3;
        int plane = (e >> 2) & 1;
        int entry = e >> 3;
        int col = entry % 66;
        int dy  = entry / 66;
        int y = y0 - 1 + dy;
        int x = col - 1;
        bool valid = ((unsigned)y < 64u) && ((unsigned)x < 64u);
        const __half* src = valid ?
            g_axh + (size_t)plane*APLSZ + ((size_t)(n*4096 + y*64 + x))*CIN + c0 + seg*8
            : g_axh;
        uint32_t dst = sb + parity*A_BUF + plane*A_PLANE + entry*80 + seg*16;
        cp16(dst, src, valid ? 16 : 0);
    }
}

__device__ __forceinline__ void load_b(int s, uint32_t sb, int k0, int tid) {
    int cc = s/9, tap = s - cc*9;
    int c0 = cc*32;
    int slot = s % 3;
#pragma unroll
    for (int r = 0; r < 4; r++) {
        int i = r*256 + tid;
        int plane = i >> 9;
        int rs = i & 511;
        int row = rs >> 2, seg = rs & 3;
        const __half* src = g_bxh + (size_t)plane*BPLSZ +
            ((size_t)tap*CIN + k0 + row)*CIN + c0 + seg*8;
        uint32_t dst = sb + B_BASE + slot*B_SLOT + plane*B_PLANE + row*80 + seg*16;
        cp16(dst, src, 16);
    }
}

__global__ void __launch_bounds__(256) mma_conv_kernel(const float* __restrict__ bias,
                                                       const float* __restrict__ sw,
                                                       const float* __restrict__ lw) {
    extern __shared__ char smem[];
    uint32_t sb = smem_u32(smem);
    int tid = threadIdx.x;
    int lane = tid & 31, w = tid >> 5;
    int wm = w & 3, wn = w >> 2;
    int g = lane >> 2, t = lane & 3;

    int q  = blockIdx.y;
    int p0 = blockIdx.x * 128;
    int n  = p0 >> 12;
    int y0 = (p0 & 4095) >> 6;
    int k0 = q * 128;

    int y_base = wm >> 1;
    int x_base = (wm & 1)*32 + ((lane>>3)&1)*8 + (lane&7);
    uint32_t aoff0 = (uint32_t)((y_base*66 + x_base)*80 + (lane>>4)*16);
    uint32_t boff0 = (uint32_t)((wn*64 + ((lane>>4)&1)*8 + (lane&7))*80 + ((lane>>3)&1)*16);

    float run[2][8][4];
    float acc[2][8][4];
#pragma unroll
    for (int mt=0; mt<2; mt++)
#pragma unroll
        for (int nt=0; nt<8; nt++)
#pragma unroll
            for (int j=0; j<4; j++) run[mt][nt][j] = 0.f;

    float fz = 0.0f;

    load_a(0, 0, sb, n, y0, tid); cp_commit();
    load_b(0, sb, k0, tid);       cp_commit();
    load_b(1, sb, k0, tid);       cp_commit();

    for (int s = 0; s < 144; s++) {
        int cc = s/9, tap = s - cc*9;
        if (s + 2 < 144) load_b(s+2, sb, k0, tid);
        if (tap == 7 && cc < 15) load_a(cc+1, (cc+1)&1, sb, n, y0, tid);
        cp_commit();
        cp_wait<2>();
        __syncthreads();

        int dy = tap/3, dx = tap - dy*3;
        uint32_t abase = sb + (cc&1)*A_BUF + aoff0 + (uint32_t)((dy*66 + dx)*80);
        uint32_t bbase = sb + B_BASE + (s%3)*B_SLOT + boff0;

#pragma unroll
        for (int ks = 0; ks < 2; ks++) {
            uint32_t kof = (uint32_t)(ks*32);
            uint32_t aH = abase + kof;
            uint32_t aL = aH + A_PLANE;
            uint32_t bH = bbase + kof;
            uint32_t bL = bH + B_PLANE;

            uint32_t ah[2][4], al[2][4], bh[8][2], bl[8][2];
            LDSM4(ah[0][0], ah[0][1], ah[0][2], ah[0][3], aH);
            LDSM4(ah[1][0], ah[1][1], ah[1][2], ah[1][3], aH + 1280);
            LDSM4(al[0][0], al[0][1], al[0][2], al[0][3], aL);
            LDSM4(al[1][0], al[1][1], al[1][2], al[1][3], aL + 1280);
            LDSM4(bh[0][0], bh[0][1], bh[1][0], bh[1][1], bH);
            LDSM4(bh[2][0], bh[2][1], bh[3][0], bh[3][1], bH + 1280);
            LDSM4(bh[4][0], bh[4][1], bh[5][0], bh[5][1], bH + 2560);
            LDSM4(bh[6][0], bh[6][1], bh[7][0], bh[7][1], bH + 3840);
            LDSM4(bl[0][0], bl[0][1], bl[1][0], bl[1][1], bL);
            LDSM4(bl[2][0], bl[2][1], bl[3][0], bl[3][1], bL + 1280);
            LDSM4(bl[4][0], bl[4][1], bl[5][0], bl[5][1], bL + 2560);
            LDSM4(bl[6][0], bl[6][1], bl[7][0], bl[7][1], bL + 3840);

            bool zc = (ks == 0) && (tap == 0 || tap == 3 || tap == 6);
#pragma unroll
            for (int mt = 0; mt < 2; mt++)
#pragma unroll
                for (int nt = 0; nt < 8; nt++) {
                    if (zc) {
                        MMA_F16_ZC(acc[mt][nt], ah[mt], bh[nt], fz);
                    } else {
                        MMA_F16(acc[mt][nt], ah[mt], bh[nt]);
                    }
                    MMA_F16(acc[mt][nt], ah[mt], bl[nt]);
                    MMA_F16(acc[mt][nt], al[mt], bh[nt]);
                }
        }
        if (tap == 2 || tap == 5 || tap == 8) {
#pragma unroll
            for (int mt = 0; mt < 2; mt++)
#pragma unroll
                for (int nt = 0; nt < 8; nt++)
#pragma unroll
                    for (int j = 0; j < 4; j++)
                        run[mt][nt][j] += acc[mt][nt][j];
        }
        __syncthreads();
    }

    // ---- Fused epilogue ----
    float* hbuf = (float*)smem;                       // [128][HSTRIDE]
    float* w2   = (float*)(smem + 128*HSTRIDE*4);     // [54][128]

#pragma unroll
    for (int mt = 0; mt < 2; mt++) {
        int lr0 = wm*32 + mt*16 + g;
#pragma unroll
        for (int nt = 0; nt < 8; nt++) {
            int lch = wn*64 + nt*8 + t*2;
            int ch = k0 + lch;
            float b0 = bias[ch], b1 = bias[ch+1];
            hbuf[lr0*HSTRIDE + lch]     = fmaxf(fmaf(run[mt][nt][0], BUNSCALE, b0), 0.f);
            hbuf[lr0*HSTRIDE + lch + 1] = fmaxf(fmaf(run[mt][nt][1], BUNSCALE, b1), 0.f);
            hbuf[(lr0+8)*HSTRIDE + lch]     = fmaxf(fmaf(run[mt][nt][2], BUNSCALE, b0), 0.f);
            hbuf[(lr0+8)*HSTRIDE + lch + 1] = fmaxf(fmaf(run[mt][nt][3], BUNSCALE, b1), 0.f);
        }
    }
    for (int e = tid; e < 54*128; e += 256) {
        int o = e >> 7, cc = e & 127;
        w2[o*128 + cc] = (o < 18) ? sw[o*CIN + k0 + cc] : lw[(o-18)*CIN + k0 + cc];
    }
    __syncthreads();

    int px0 = tid & 63, og = tid >> 6;
#pragma unroll
    for (int half = 0; half < 2; half++) {
        int px = half*64 + px0;
        float hacc[14];
#pragma unroll
        for (int t14 = 0; t14 < 14; t14++) hacc[t14] = 0.f;
#pragma unroll 2
        for (int cc4 = 0; cc4 < 32; cc4++) {
            float4 hv = *(const float4*)&hbuf[px*HSTRIDE + cc4*4];
#pragma unroll
            for (int t14 = 0; t14 < 14; t14++) {
                int o = og + 4*t14;
                if (o < 54) {
                    float4 wv = *(const float4*)&w2[o*128 + cc4*4];
                    hacc[t14] = fmaf(wv.x, hv.x, hacc[t14]);
                    hacc[t14] = fmaf(wv.y, hv.y, hacc[t14]);
                    hacc[t14] = fmaf(wv.z, hv.z, hacc[t14]);
                    hacc[t14] = fmaf(wv.w, hv.w, hacc[t14]);
                }
            }
        }
        int pix = (p0 & 4095) + px;
#pragma unroll
        for (int t14 = 0; t14 < 14; t14++) {
            int o = og + 4*t14;
            if (o < 54)
                g_part[((size_t)((q*2+n)*56 + o))*4096 + pix] = hacc[t14];
        }
    }
}

// ---------------------------------------------------------------------------
// Anchor
// ---------------------------------------------------------------------------
__device__ __forceinline__ void anchor_calc(int y, int x, int k,
                                            float& o0, float& o1, float& o2, float& o3) {
    const double ratios[3] = {0.5, 1.0, 2.0};
    const double scales[3] = {8.0, 16.0, 32.0};
    int i = k/3, j = k%3;
    double h = 16.0*scales[j]*sqrt(ratios[i]);
    double w = 16.0*scales[j]*sqrt(1.0/ratios[i]);
    float b0 = (float)(8.0 - h*0.5);
    float b1 = (float)(8.0 - w*0.5);
    float b2 = (float)(8.0 + h*0.5);
    float b3 = (float)(8.0 + w*0.5);
    o0 = (float)((double)b0 + (double)(y*16));
    o1 = (float)((double)b1 + (double)(x*16));
    o2 = (float)((double)b2 + (double)(y*16));
    o3 = (float)((double)b3 + (double)(x*16));
}

__device__ __forceinline__ float load_dim(const void* p) {
    int iv = *(const int*)p;
    if (iv > 0 && iv < (1<<20)) return (float)iv;
    return *(const float*)p;
}

// ---------------------------------------------------------------------------
// Finalize. grid (128, 2): 32-pixel blocks.
// ---------------------------------------------------------------------------
__global__ __launch_bounds__(256) void finalize_kernel(const float* __restrict__ sb,
                                                       const float* __restrict__ lb,
                                                       const void* ihp, const void* iwp,
                                                       float* __restrict__ out) {
    __shared__ float s_o[54][32];
    int blk = blockIdx.x;
    int y = blk >> 1;
    int ph = (blk & 1) * 32;
    int n = blockIdx.y;
    int tid = threadIdx.x;

    for (int e=tid; e<1728; e+=256) {
        int px = e & 31, o = e >> 5;
        size_t base = (size_t)y*64 + ph + px;
        float s = 0.f;
#pragma unroll
        for (int q = 0; q < NQ; q++)
            s += g_part[((size_t)((q*2+n)*56 + o))*4096 + base];
        s += (o<18) ? sb[o] : lb[o-18];
        s_o[o][px] = s;
        int pix = y*64 + ph + px;
        if (o < 18)
            out[OFF_SCORES + ((size_t)n*ATOT + (size_t)pix*9 + (o>>1))*2 + (o&1)] = s;
        else {
            int c = o-18;
            out[OFF_LOCS + ((size_t)n*ATOT + (size_t)pix*9 + (c>>2))*4 + (c&3)] = s;
        }
    }
    __syncthreads();

    float img_h = load_dim(ihp), img_w = load_dim(iwp);

    for (int e=tid; e<288; e+=256) {
        int p2 = e & 31;
        int k  = e >> 5;
        float s0 = s_o[2*k][p2], s1 = s_o[2*k+1][p2];
        float m  = fmaxf(s0,s1);
        float e0 = expf(s0-m), e1 = expf(s1-m);
        float fg = e1/(e0+e1);

        float d0 = s_o[18+4*k+0][p2];
        float d1 = s_o[18+4*k+1][p2];
        float d2 = s_o[18+4*k+2][p2];
        float d3 = s_o[18+4*k+3][p2];

        int xcol = ph + p2;
        float a0,a1,a2,a3;
        anchor_calc(y, xcol, k, a0,a1,a2,a3);

        float ah = a2-a0, aw = a3-a1;
        float acy = a0 + 0.5f*ah, acx = a1 + 0.5f*aw;
        float cy = fmaf(d0, ah, acy);
        float cx = fmaf(d1, aw, acx);
        float h  = expf(d2)*ah;
        float w  = expf(d3)*aw;
        float r0 = fminf(fmaxf(cy-0.5f*h, 0.f), img_h);
        float r1 = fminf(fmaxf(cx-0.5f*w, 0.f), img_w);
        float r2 = fminf(fmaxf(cy+0.5f*h, 0.f), img_h);
        float r3 = fminf(fmaxf(cx+0.5f*w, 0.f), img_w);
        bool valid = (r2-r0 >= 16.f) && (r3-r1 >= 16.f);

        int aidx = (y*64 + xcol)*9 + k;
        int gi = n*ATOT + aidx;
        float sc = valid ? fg : -CUDART_INF_F;
        g_score[gi] = sc;
        g_roi[gi] = make_float4(r0,r1,r2,r3);
        uint32_t u = valid ? __float_as_uint(fg) : 0u;
        g_key32[gi] = u | ((uint32_t)(1 - n) << 30);
        g_val[gi] = gi;
        if (n == 0) {
            out[OFF_ANCHOR + (size_t)aidx*4 + 0] = a0;
            out[OFF_ANCHOR + (size_t)aidx*4 + 1] = a1;
            out[OFF_ANCHOR + (size_t)aidx*4 + 2] = a2;
            out[OFF_ANCHOR + (size_t)aidx*4 + 3] = a3;
        }
    }
}

// ---------------------------------------------------------------------------
// Gather top-6000 boxes + scores after sort
// ---------------------------------------------------------------------------
__global__ void gather_kernel() {
    int t = blockIdx.x*256 + threadIdx.x;
    if (t >= NB*NPRE) return;
    int n = t/NPRE, i = t%NPRE;
    int gi = g_val_out[n*ATOT + i];
    g_boxes[t] = g_roi[gi];
    g_boxsc[t] = g_score[gi];
}

// ---------------------------------------------------------------------------
// NMS bitmask: 256 threads, 4 i-rows (of 64) per block; triangle-skip.
// grid (94 jb, 24 ib4, 2 n)
// ---------------------------------------------------------------------------
__global__ __launch_bounds__(256) void mask_kernel() {
    int n   = blockIdx.z;
    int jb  = blockIdx.x;
    int ib4 = blockIdx.y;
    if (jb < ib4*4) return;                 // all 4 rows below diagonal
    int t   = threadIdx.x;
    int ib  = ib4*4 + (t >> 6);
    int ti  = t & 63;

    __shared__ float4 cb[64];
    if (t < 64) {
        int j = jb*64 + t;
        cb[t] = (j < NPRE) ? g_boxes[n*NPRE + j] : make_float4(0.f,0.f,0.f,0.f);
    }
    __syncthreads();

    if (jb < ib || ib >= MASKW) return;     // per-row triangle / bounds
    int i = ib*64 + ti;
    if (i >= NPRE) return;
    float4 bi = g_boxes[n*NPRE + i];
    float areai = (bi.z-bi.x)*(bi.w-bi.y);

    unsigned long long word = 0ull;
    int jmax = min(64, NPRE - jb*64);
    for (int jj=0; jj<jmax; jj++) {
        float4 bj = cb[jj];
        float areaj = (bj.z-bj.x)*(bj.w-bj.y);
        float ih = fmaxf(fminf(bi.z,bj.z) - fmaxf(bi.x,bj.x), 0.f);
        float iw = fmaxf(fminf(bi.w,bj.w) - fmaxf(bi.y,bj.y), 0.f);
        float inter = ih*iw;
        float iou = inter/(areai + areaj - inter + 1e-9f);
        if (iou > NMS_T) word |= (1ull << jj);
    }
    g_mask[((size_t)n*NPRE + i)*MASKW + jb] = word;
}

// ---------------------------------------------------------------------------
// Greedy NMS scan + fused output. Dual suppression accumulators (MLP 2).
// ---------------------------------------------------------------------------
__global__ void scan_kernel(float* __restrict__ out) {
    int n = blockIdx.x;
    int lane = threadIdx.x;
    const unsigned FULL = 0xffffffffu;

    unsigned long long r0a=0ull, r1a=0ull, r2a=0ull;
    unsigned long long r0b=0ull, r1b=0ull, r2b=0ull;
    int cnt = 0;
    const unsigned long long* mk = g_mask + (size_t)n*NPRE*MASKW;
    const float* sc = g_boxsc + n*NPRE;

    unsigned long long m0, m1;
    float s0, s1;
    {
        int i0 = lane, i1 = 32 + lane;
        m0 = mk[(size_t)i0*MASKW];
        m1 = mk[(size_t)i1*MASKW];
        s0 = sc[i0];
        s1 = sc[i1];
    }

    for (int ch=0; ch<MASKW; ch++) {
        unsigned long long nm0 = 0ull, nm1 = 0ull;
        float ns0 = -CUDART_INF_F, ns1 = -CUDART_INF_F;
        if (ch + 1 < MASKW) {
            int i0 = (ch+1)*64 + lane, i1 = i0 + 32;
            if (i0 < NPRE) { nm0 = mk[(size_t)i0*MASKW + ch + 1]; ns0 = sc[i0]; }
            if (i1 < NPRE) { nm1 = mk[(size_t)i1*MASKW + ch + 1]; ns1 = sc[i1]; }
        }

        unsigned inv0 = __ballot_sync(FULL, !isfinite(s0));
        unsigned inv1 = __ballot_sync(FULL, !isfinite(s1));
        unsigned long long W = (unsigned long long)inv0 | ((unsigned long long)inv1 << 32);

        int seg = ch >> 5, ln = ch & 31;
        unsigned long long rra = (seg==0) ? r0a : ((seg==1) ? r1a : r2a);
        unsigned long long rrb = (seg==0) ? r0b : ((seg==1) ? r1b : r2b);
        W |= __shfl_sync(FULL, rra | rrb, ln);

        unsigned long long keptb = 0ull;
        while (~W) {
            int p = __ffsll((long long)(~W)) - 1;
            keptb |= (1ull << p);
            if (lane == 0) g_kept[n*NPOST + cnt] = ch*64 + p;
            cnt++;
            if (cnt == NPOST) break;
            unsigned long long rw = __shfl_sync(FULL, (p<32) ? m0 : m1, p & 31);
            W |= rw;
        }
        if (cnt >= NPOST) break;

        // OR suppression rows with two independent accumulator sets (MLP 2)
        unsigned long long kb = keptb;
        bool tog = false;
        while (kb) {
            int p = __ffsll((long long)kb) - 1;
            kb &= kb - 1;
            size_t row = (size_t)(ch*64 + p)*MASKW;
            if (!tog) {
                r0a |= mk[row + lane];
                r1a |= mk[row + 32 + lane];
                if (64 + lane < MASKW) r2a |= mk[row + 64 + lane];
            } else {
                r0b |= mk[row + lane];
                r1b |= mk[row + 32 + lane];
                if (64 + lane < MASKW) r2b |= mk[row + 64 + lane];
            }
            tog = !tog;
        }

        m0 = nm0; m1 = nm1; s0 = ns0; s1 = ns1;
    }

    __threadfence_block();
    __syncwarp(FULL);
    for (int r = lane; r < NPOST; r += 32) {
        float4 b = make_float4(0.f,0.f,0.f,0.f);
        float vm = 0.f;
        if (r < cnt) {
            b = g_boxes[n*NPRE + g_kept[n*NPOST + r]];
            vm = 1.f;
        }
        size_t t = (size_t)n*NPOST + r;
        out[OFF_ROIS + t*4 + 0] = b.x;
        out[OFF_ROIS + t*4 + 1] = b.y;
        out[OFF_ROIS + t*4 + 2] = b.z;
        out[OFF_ROIS + t*4 + 3] = b.w;
        out[OFF_RIDX + t]  = (float)n;
        out[OFF_VMASK + t] = vm;
    }
}

// ---------------------------------------------------------------------------
// Launch
// ---------------------------------------------------------------------------
extern "C" void kernel_launch(void* const* d_in, const int* in_sizes, int n_in,
                              void* d_out, int out_size) {
    const float* x  = (const float*)d_in[0];
    const float* w  = (const float*)d_in[1];
    const float* b  = (const float*)d_in[2];
    const float* sw = (const float*)d_in[3];
    const float* sb = (const float*)d_in[4];
    const float* lw = (const float*)d_in[5];
    const float* lb = (const float*)d_in[6];
    float* out = (float*)d_out;

    cudaFuncSetAttribute(mma_conv_kernel,
                         cudaFuncAttributeMaxDynamicSharedMemorySize, SMEM_DYN);

    split_kernel<<<dim3(128, 16, 3), 256>>>(x, w);      // launch 1
    noop_kernel<<<1, 1>>>();                            // launch 2
    noop_kernel<<<1, 1>>>();                            // launch 3
    mma_conv_kernel<<<dim3(64, 4), 256, SMEM_DYN>>>(b, sw, lw);   // launch 4 (profiled)
    finalize_kernel<<<dim3(128, 2), 256>>>(sb, lb, d_in[7], d_in[8], out);

    void* tmp;
    uint32_t *ki, *ko;
    int *vi, *vo;
    cudaGetSymbolAddress(&tmp, g_cub_temp);
    cudaGetSymbolAddress((void**)&ki, g_key32);
    cudaGetSymbolAddress((void**)&ko, g_key32_out);
    cudaGetSymbolAddress((void**)&vi, g_val);
    cudaGetSymbolAddress((void**)&vo, g_val_out);

    {
        size_t tb = 0;
        cub::DeviceRadixSort::SortPairsDescending(nullptr, tb,
            ki, ko, vi, vo, NB*ATOT, 0, 31, (cudaStream_t)0);
        if (tb <= sizeof(g_cub_temp)) {
            cub::DeviceRadixSort::SortPairsDescending(tmp, tb,
                ki, ko, vi, vo, NB*ATOT, 0, 31, (cudaStream_t)0);
        }
    }

    gather_kernel<<<(NB*NPRE + 255)/256, 256>>>();
    mask_kernel<<<dim3(MASKW, 24, NB), 256>>>();
    scan_kernel<<<NB, 32>>>(out);
}

// round 14
// speedup vs baseline: 1.0386x; 1.0386x over previous
#include <cuda_runtime.h>
#include <cuda_bf16.h>
#include <cuda_fp16.h>
#include <math_constants.h>
#include <cub/cub.cuh>
#include <cstdint>

// ---------------------------------------------------------------------------
// Problem constants
// ---------------------------------------------------------------------------
#define HH 64
#define WWID 64
#define CIN 512
#define NB 2
#define NANCH 9
#define ATOT (HH*WWID*NANCH)      // 36864
#define NPRE 6000
#define NPOST 300
#define MASKW 94                  // ceil(6000/64)
#define NMS_T 0.7f

#define MTOT (NB*HH*WWID)         // 8192 pixel rows
#define KTAP 9

// Output layout (float32, concatenated in reference return order)
#define OFF_LOCS   0
#define OFF_SCORES (NB*ATOT*4)
#define OFF_ROIS   (OFF_SCORES + NB*ATOT*2)
#define OFF_RIDX   (OFF_ROIS + NB*NPOST*4)
#define OFF_ANCHOR (OFF_RIDX + NB*NPOST)
#define OFF_VMASK  (OFF_ANCHOR + ATOT*4)

#define APLSZ ((size_t)MTOT*CIN)        // elements per A fp16 plane
#define BPLSZ ((size_t)KTAP*CIN*CIN)    // elements per B fp16 plane
#define BSCALE 64.0f
#define BUNSCALE 0.015625f
#define NQ 4                             // heads channel-split = conv N-tiles

// ---------------------------------------------------------------------------
// Scratch
// ---------------------------------------------------------------------------
__device__ __half g_axh[2*APLSZ];                // input fp16 planes (NHWC)
__device__ __half g_bxh[2*BPLSZ];                // weight planes [tap][k][c], x64
__device__ float g_part[(size_t)NQ*NB*56*4096]; // heads partials [q][n][o][pix]
__device__ float g_score[NB*ATOT];
__device__ uint32_t g_key32[NB*ATOT];
__device__ uint32_t g_key32_out[NB*ATOT];
__device__ int   g_val[NB*ATOT];
__device__ int   g_val_out[NB*ATOT];
__device__ float4 g_roi[NB*ATOT];
__device__ float4 g_boxes[NB*NPRE];
__device__ float g_boxsc[NB*NPRE];
__device__ unsigned long long g_mask[(size_t)NB*NPRE*MASKW];
__device__ int g_kept[NB*NPOST];
__device__ __align__(256) unsigned char g_cub_temp[8<<20];

// ---------------------------------------------------------------------------
// PTX helpers
// ---------------------------------------------------------------------------
__device__ __forceinline__ uint32_t smem_u32(const void* p) {
    uint32_t a;
    asm("{ .reg .u64 t; cvta.to.shared.u64 t, %1; cvt.u32.u64 %0, t; }" : "=r"(a) : "l"(p));
    return a;
}
__device__ __forceinline__ void cp16(uint32_t dst, const void* src, int srcsize) {
    asm volatile("cp.async.cg.shared.global [%0], [%1], 16, %2;"
                 :: "r"(dst), "l"(src), "r"(srcsize) : "memory");
}
__device__ __forceinline__ void cp_commit() { asm volatile("cp.async.commit_group;" ::: "memory"); }
template<int N> __device__ __forceinline__ void cp_wait() {
    asm volatile("cp.async.wait_group %0;" :: "n"(N) : "memory");
}

#define LDSM4(r0, r1, r2, r3, a) \
    asm volatile("ldmatrix.sync.aligned.m8n8.x4.shared.b16 {%0,%1,%2,%3}, [%4];" \
                 : "=r"(r0), "=r"(r1), "=r"(r2), "=r"(r3) : "r"(a))

// fp16 2-way split
__device__ __forceinline__ void f16split(float v, __half& o0, __half& o1) {
    __half h0 = __float2half_rn(v);
    float r = v - __half2float(h0);
    o0 = h0;
    o1 = __float2half_rn(r);
}

#define MMA_F16(d, a, b) \
    asm volatile("mma.sync.aligned.m16n8k16.row.col.f32.f16.f16.f32 " \
                 "{%0,%1,%2,%3},{%4,%5,%6,%7},{%8,%9},{%0,%1,%2,%3};" \
                 : "+f"((d)[0]), "+f"((d)[1]), "+f"((d)[2]), "+f"((d)[3]) \
                 : "r"((a)[0]), "r"((a)[1]), "r"((a)[2]), "r"((a)[3]), \
                   "r"((b)[0]), "r"((b)[1]))

#define MMA_F16_ZC(d, a, b, z) \
    asm volatile("mma.sync.aligned.m16n8k16.row.col.f32.f16.f16.f32 " \
                 "{%0,%1,%2,%3},{%4,%5,%6,%7},{%8,%9},{%10,%10,%10,%10};" \
                 : "=f"((d)[0]), "=f"((d)[1]), "=f"((d)[2]), "=f"((d)[3]) \
                 : "r"((a)[0]), "r"((a)[1]), "r"((a)[2]), "r"((a)[3]), \
                   "r"((b)[0]), "r"((b)[1]), "f"(z))

// ---------------------------------------------------------------------------
// Combined input/weight split. grid (128, 16, 3).
// ---------------------------------------------------------------------------
__global__ void split_kernel(const float* __restrict__ x, const float* __restrict__ w) {
    if (blockIdx.z < 2) {
        __shared__ float tile[32][33];
        int pt = blockIdx.x, ct = blockIdx.y, n = blockIdx.z;
        int tx = threadIdx.x & 31, ty = threadIdx.x >> 5;
#pragma unroll
        for (int r = 0; r < 4; r++) {
            int c = ct*32 + ty + r*8;
            int p = pt*32 + tx;
            tile[ty + r*8][tx] = x[((size_t)(n*CIN + c))*4096 + p];
        }
        __syncthreads();
        int cl = (threadIdx.x & 15)*2;
        int pl0 = threadIdx.x >> 4;
#pragma unroll
        for (int r = 0; r < 2; r++) {
            int pl = pl0 + r*16;
            int pg = pt*32 + pl;
            int cg = ct*32 + cl;
            float a0 = tile[cl][pl];
            float a1 = tile[cl+1][pl];
            __half h00, h01, h10, h11;
            f16split(a0, h00, h01);
            f16split(a1, h10, h11);
            size_t o = ((size_t)(n*4096 + pg))*CIN + cg;
            *(__half2*)&g_axh[o] = __halves2half2(h00, h10);
            *(__half2*)&g_axh[APLSZ + o] = __halves2half2(h01, h11);
        }
    } else {
        int base = (blockIdx.y*128 + blockIdx.x)*256 + threadIdx.x;
        for (int e = base; e < KTAP*CIN*CIN; e += 128*16*256) {
            int c = e & 511;
            int k = (e >> 9) & 511;
            int tap = e >> 18;
            float v = w[((size_t)k*CIN + c)*KTAP + tap] * BSCALE;
            __half h0, h1;
            f16split(v, h0, h1);
            g_bxh[e] = h0;
            g_bxh[BPLSZ + e] = h1;
        }
    }
}

// ---------------------------------------------------------------------------
// fp16x3 emulated-fp32 conv GEMM, cin-major / tap-minor, 512 threads / 16 warps.
// CTA tile M=128 x N=128; warp tile 32x32 (wm=w&3 rows, wn=w>>2 cols).
// 4 warps per SMSP -> tensor-pipe latency hiding (was 2).
// Windows drain at taps 2,5,8 (96 K) -- numerics identical to round 12.
// ---------------------------------------------------------------------------
#define A_PLANE 21120
#define A_BUF   42240
#define B_BASE  84480
#define B_SLOT  20480
#define B_PLANE 10240
#define SMEM_DYN 145920
#define HSTRIDE 132
#define CTHREADS 512

__device__ __forceinline__ void load_a(int cc, int parity, uint32_t sb,
                                       int n, int y0, int tid) {
    int c0 = cc*32;
    for (int e = tid; e < 2112; e += CTHREADS) {
        int seg = e & 3;
        int plane = (e >> 2) & 1;
        int entry = e >> 3;
        int col = entry % 66;
        int dy  = entry / 66;
        int y = y0 - 1 + dy;
        int x = col - 1;
        bool valid = ((unsigned)y < 64u) && ((unsigned)x < 64u);
        const __half* src = valid ?
            g_axh + (size_t)plane*APLSZ + ((size_t)(n*4096 + y*64 + x))*CIN + c0 + seg*8
            : g_axh;
        uint32_t dst = sb + parity*A_BUF + plane*A_PLANE + entry*80 + seg*16;
        cp16(dst, src, valid ? 16 : 0);
    }
}

__device__ __forceinline__ void load_b(int s, uint32_t sb, int k0, int tid) {
    int cc = s/9, tap = s - cc*9;
    int c0 = cc*32;
    int slot = s % 3;
#pragma unroll
    for (int r = 0; r < 2; r++) {
        int i = r*CTHREADS + tid;
        int plane = i >> 9;
        int rs = i & 511;
        int row = rs >> 2, seg = rs & 3;
        const __half* src = g_bxh + (size_t)plane*BPLSZ +
            ((size_t)tap*CIN + k0 + row)*CIN + c0 + seg*8;
        uint32_t dst = sb + B_BASE + slot*B_SLOT + plane*B_PLANE + row*80 + seg*16;
        cp16(dst, src, 16);
    }
}

__global__ void __launch_bounds__(CTHREADS, 1) mma_conv_kernel(const float* __restrict__ bias,
                                                               const float* __restrict__ sw,
                                                               const float* __restrict__ lw) {
    extern __shared__ char smem[];
    uint32_t sb = smem_u32(smem);
    int tid = threadIdx.x;
    int lane = tid & 31, w = tid >> 5;       // 16 warps
    int wm = w & 3, wn = w >> 2;             // 4 x 4 warp grid, 32x32 tiles
    int g = lane >> 2, t = lane & 3;

    int q  = blockIdx.y;
    int p0 = blockIdx.x * 128;
    int n  = p0 >> 12;
    int y0 = (p0 & 4095) >> 6;
    int k0 = q * 128;

    // A fragment rows: wm*32 + mt*16 + {0,8} + (lane&7); band entry mapping
    int y_base = wm >> 1;
    int x_base = (wm & 1)*32 + ((lane>>3)&1)*8 + (lane&7);
    uint32_t aoff0 = (uint32_t)((y_base*66 + x_base)*80 + (lane>>4)*16);
    // B fragment rows: wn*32 + {0,8} + (lane&7), 2 n8-tiles per LDSM4
    uint32_t boff0 = (uint32_t)((wn*32 + ((lane>>4)&1)*8 + (lane&7))*80 + ((lane>>3)&1)*16);

    float run[2][4][4];
    float acc[2][4][4];
#pragma unroll
    for (int mt=0; mt<2; mt++)
#pragma unroll
        for (int nt=0; nt<4; nt++)
#pragma unroll
            for (int j=0; j<4; j++) run[mt][nt][j] = 0.f;

    float fz = 0.0f;

    load_a(0, 0, sb, n, y0, tid); cp_commit();
    load_b(0, sb, k0, tid);       cp_commit();
    load_b(1, sb, k0, tid);       cp_commit();

    for (int s = 0; s < 144; s++) {
        int cc = s/9, tap = s - cc*9;
        if (s + 2 < 144) load_b(s+2, sb, k0, tid);
        if (tap == 7 && cc < 15) load_a(cc+1, (cc+1)&1, sb, n, y0, tid);
        cp_commit();
        cp_wait<2>();
        __syncthreads();

        int dy = tap/3, dx = tap - dy*3;
        uint32_t abase = sb + (cc&1)*A_BUF + aoff0 + (uint32_t)((dy*66 + dx)*80);
        uint32_t bbase = sb + B_BASE + (s%3)*B_SLOT + boff0;

#pragma unroll
        for (int ks = 0; ks < 2; ks++) {
            uint32_t kof = (uint32_t)(ks*32);
            uint32_t aH = abase + kof;
            uint32_t aL = aH + A_PLANE;
            uint32_t bH = bbase + kof;
            uint32_t bL = bH + B_PLANE;

            uint32_t ah[2][4], al[2][4], bh[4][2], bl[4][2];
            LDSM4(ah[0][0], ah[0][1], ah[0][2], ah[0][3], aH);
            LDSM4(ah[1][0], ah[1][1], ah[1][2], ah[1][3], aH + 1280);
            LDSM4(al[0][0], al[0][1], al[0][2], al[0][3], aL);
            LDSM4(al[1][0], al[1][1], al[1][2], al[1][3], aL + 1280);
            LDSM4(bh[0][0], bh[0][1], bh[1][0], bh[1][1], bH);
            LDSM4(bh[2][0], bh[2][1], bh[3][0], bh[3][1], bH + 1280);
            LDSM4(bl[0][0], bl[0][1], bl[1][0], bl[1][1], bL);
            LDSM4(bl[2][0], bl[2][1], bl[3][0], bl[3][1], bL + 1280);

            bool zc = (ks == 0) && (tap == 0 || tap == 3 || tap == 6);
#pragma unroll
            for (int mt = 0; mt < 2; mt++)
#pragma unroll
                for (int nt = 0; nt < 4; nt++) {
                    if (zc) {
                        MMA_F16_ZC(acc[mt][nt], ah[mt], bh[nt], fz);
                    } else {
                        MMA_F16(acc[mt][nt], ah[mt], bh[nt]);
                    }
                    MMA_F16(acc[mt][nt], ah[mt], bl[nt]);
                    MMA_F16(acc[mt][nt], al[mt], bh[nt]);
                }
        }
        if (tap == 2 || tap == 5 || tap == 8) {
#pragma unroll
            for (int mt = 0; mt < 2; mt++)
#pragma unroll
                for (int nt = 0; nt < 4; nt++)
#pragma unroll
                    for (int j = 0; j < 4; j++)
                        run[mt][nt][j] += acc[mt][nt][j];
        }
        __syncthreads();
    }

    // ---- Fused epilogue: h tile -> smem, heads 1x1 partials -> g_part ----
    float* hbuf = (float*)smem;                       // [128][HSTRIDE]
    float* w2   = (float*)(smem + 128*HSTRIDE*4);     // [54][128]

#pragma unroll
    for (int mt = 0; mt < 2; mt++) {
        int lr0 = wm*32 + mt*16 + g;
#pragma unroll
        for (int nt = 0; nt < 4; nt++) {
            int lch = wn*32 + nt*8 + t*2;
            int ch = k0 + lch;
            float b0 = bias[ch], b1 = bias[ch+1];
            hbuf[lr0*HSTRIDE + lch]     = fmaxf(fmaf(run[mt][nt][0], BUNSCALE, b0), 0.f);
            hbuf[lr0*HSTRIDE + lch + 1] = fmaxf(fmaf(run[mt][nt][1], BUNSCALE, b1), 0.f);
            hbuf[(lr0+8)*HSTRIDE + lch]     = fmaxf(fmaf(run[mt][nt][2], BUNSCALE, b0), 0.f);
            hbuf[(lr0+8)*HSTRIDE + lch + 1] = fmaxf(fmaf(run[mt][nt][3], BUNSCALE, b1), 0.f);
        }
    }
    for (int e = tid; e < 54*128; e += CTHREADS) {
        int o = e >> 7, cc = e & 127;
        w2[o*128 + cc] = (o < 18) ? sw[o*CIN + k0 + cc] : lw[(o-18)*CIN + k0 + cc];
    }
    __syncthreads();

    int px = tid & 127, og = tid >> 7;     // 128 pixels x 4 output groups
    {
        float hacc[14];
#pragma unroll
        for (int t14 = 0; t14 < 14; t14++) hacc[t14] = 0.f;
#pragma unroll 2
        for (int cc4 = 0; cc4 < 32; cc4++) {
            float4 hv = *(const float4*)&hbuf[px*HSTRIDE + cc4*4];
#pragma unroll
            for (int t14 = 0; t14 < 14; t14++) {
                int o = og + 4*t14;
                if (o < 54) {
                    float4 wv = *(const float4*)&w2[o*128 + cc4*4];
                    hacc[t14] = fmaf(wv.x, hv.x, hacc[t14]);
                    hacc[t14] = fmaf(wv.y, hv.y, hacc[t14]);
                    hacc[t14] = fmaf(wv.z, hv.z, hacc[t14]);
                    hacc[t14] = fmaf(wv.w, hv.w, hacc[t14]);
                }
            }
        }
        int pix = (p0 & 4095) + px;
#pragma unroll
        for (int t14 = 0; t14 < 14; t14++) {
            int o = og + 4*t14;
            if (o < 54)
                g_part[((size_t)((q*2+n)*56 + o))*4096 + pix] = hacc[t14];
        }
    }
}

// ---------------------------------------------------------------------------
// Anchor
// ---------------------------------------------------------------------------
__device__ __forceinline__ void anchor_calc(int y, int x, int k,
                                            float& o0, float& o1, float& o2, float& o3) {
    const double ratios[3] = {0.5, 1.0, 2.0};
    const double scales[3] = {8.0, 16.0, 32.0};
    int i = k/3, j = k%3;
    double h = 16.0*scales[j]*sqrt(ratios[i]);
    double w = 16.0*scales[j]*sqrt(1.0/ratios[i]);
    float b0 = (float)(8.0 - h*0.5);
    float b1 = (float)(8.0 - w*0.5);
    float b2 = (float)(8.0 + h*0.5);
    float b3 = (float)(8.0 + w*0.5);
    o0 = (float)((double)b0 + (double)(y*16));
    o1 = (float)((double)b1 + (double)(x*16));
    o2 = (float)((double)b2 + (double)(y*16));
    o3 = (float)((double)b3 + (double)(x*16));
}

__device__ __forceinline__ float load_dim(const void* p) {
    int iv = *(const int*)p;
    if (iv > 0 && iv < (1<<20)) return (float)iv;
    return *(const float*)p;
}

// ---------------------------------------------------------------------------
// Finalize. grid (128, 2): 32-pixel blocks.
// ---------------------------------------------------------------------------
__global__ __launch_bounds__(256) void finalize_kernel(const float* __restrict__ sb,
                                                       const float* __restrict__ lb,
                                                       const void* ihp, const void* iwp,
                                                       float* __restrict__ out) {
    __shared__ float s_o[54][32];
    int blk = blockIdx.x;
    int y = blk >> 1;
    int ph = (blk & 1) * 32;
    int n = blockIdx.y;
    int tid = threadIdx.x;

    for (int e=tid; e<1728; e+=256) {
        int px = e & 31, o = e >> 5;
        size_t base = (size_t)y*64 + ph + px;
        float s = 0.f;
#pragma unroll
        for (int q = 0; q < NQ; q++)
            s += g_part[((size_t)((q*2+n)*56 + o))*4096 + base];
        s += (o<18) ? sb[o] : lb[o-18];
        s_o[o][px] = s;
        int pix = y*64 + ph + px;
        if (o < 18)
            out[OFF_SCORES + ((size_t)n*ATOT + (size_t)pix*9 + (o>>1))*2 + (o&1)] = s;
        else {
            int c = o-18;
            out[OFF_LOCS + ((size_t)n*ATOT + (size_t)pix*9 + (c>>2))*4 + (c&3)] = s;
        }
    }
    __syncthreads();

    float img_h = load_dim(ihp), img_w = load_dim(iwp);

    for (int e=tid; e<288; e+=256) {
        int p2 = e & 31;
        int k  = e >> 5;
        float s0 = s_o[2*k][p2], s1 = s_o[2*k+1][p2];
        float m  = fmaxf(s0,s1);
        float e0 = expf(s0-m), e1 = expf(s1-m);
        float fg = e1/(e0+e1);

        float d0 = s_o[18+4*k+0][p2];
        float d1 = s_o[18+4*k+1][p2];
        float d2 = s_o[18+4*k+2][p2];
        float d3 = s_o[18+4*k+3][p2];

        int xcol = ph + p2;
        float a0,a1,a2,a3;
        anchor_calc(y, xcol, k, a0,a1,a2,a3);

        float ah = a2-a0, aw = a3-a1;
        float acy = a0 + 0.5f*ah, acx = a1 + 0.5f*aw;
        float cy = fmaf(d0, ah, acy);
        float cx = fmaf(d1, aw, acx);
        float h  = expf(d2)*ah;
        float w  = expf(d3)*aw;
        float r0 = fminf(fmaxf(cy-0.5f*h, 0.f), img_h);
        float r1 = fminf(fmaxf(cx-0.5f*w, 0.f), img_w);
        float r2 = fminf(fmaxf(cy+0.5f*h, 0.f), img_h);
        float r3 = fminf(fmaxf(cx+0.5f*w, 0.f), img_w);
        bool valid = (r2-r0 >= 16.f) && (r3-r1 >= 16.f);

        int aidx = (y*64 + xcol)*9 + k;
        int gi = n*ATOT + aidx;
        float sc = valid ? fg : -CUDART_INF_F;
        g_score[gi] = sc;
        g_roi[gi] = make_float4(r0,r1,r2,r3);
        uint32_t u = valid ? __float_as_uint(fg) : 0u;
        g_key32[gi] = u | ((uint32_t)(1 - n) << 30);
        g_val[gi] = gi;
        if (n == 0) {
            out[OFF_ANCHOR + (size_t)aidx*4 + 0] = a0;
            out[OFF_ANCHOR + (size_t)aidx*4 + 1] = a1;
            out[OFF_ANCHOR + (size_t)aidx*4 + 2] = a2;
            out[OFF_ANCHOR + (size_t)aidx*4 + 3] = a3;
        }
    }
}

// ---------------------------------------------------------------------------
// Gather top-6000 boxes + scores after sort
// ---------------------------------------------------------------------------
__global__ void gather_kernel() {
    int t = blockIdx.x*256 + threadIdx.x;
    if (t >= NB*NPRE) return;
    int n = t/NPRE, i = t%NPRE;
    int gi = g_val_out[n*ATOT + i];
    g_boxes[t] = g_roi[gi];
    g_boxsc[t] = g_score[gi];
}

// ---------------------------------------------------------------------------
// NMS bitmask (round-12 form: 64 threads, upper triangle)
// ---------------------------------------------------------------------------
__global__ __launch_bounds__(64) void mask_kernel() {
    int n  = blockIdx.z;
    int jb = blockIdx.x;
    int ib = blockIdx.y;
    if (jb < ib) return;
    int t  = threadIdx.x;

    __shared__ float4 cb[64];
    int j = jb*64 + t;
    cb[t] = (j < NPRE) ? g_boxes[n*NPRE + j] : make_float4(0.f,0.f,0.f,0.f);
    __syncthreads();

    int i = ib*64 + t;
    if (i >= NPRE) return;
    float4 bi = g_boxes[n*NPRE + i];
    float areai = (bi.z-bi.x)*(bi.w-bi.y);

    unsigned long long word = 0ull;
    int jmax = min(64, NPRE - jb*64);
    for (int jj=0; jj<jmax; jj++) {
        float4 bj = cb[jj];
        float areaj = (bj.z-bj.x)*(bj.w-bj.y);
        float ih = fmaxf(fminf(bi.z,bj.z) - fmaxf(bi.x,bj.x), 0.f);
        float iw = fmaxf(fminf(bi.w,bj.w) - fmaxf(bi.y,bj.y), 0.f);
        float inter = ih*iw;
        float iou = inter/(areai + areaj - inter + 1e-9f);
        if (iou > NMS_T) word |= (1ull << jj);
    }
    g_mask[((size_t)n*NPRE + i)*MASKW + jb] = word;
}

// ---------------------------------------------------------------------------
// Greedy NMS scan + fused output (round-12 form: single accumulators)
// ---------------------------------------------------------------------------
__global__ void scan_kernel(float* __restrict__ out) {
    int n = blockIdx.x;
    int lane = threadIdx.x;
    const unsigned FULL = 0xffffffffu;

    unsigned long long r0=0ull, r1=0ull, r2=0ull;
    int cnt = 0;
    const unsigned long long* mk = g_mask + (size_t)n*NPRE*MASKW;
    const float* sc = g_boxsc + n*NPRE;

    unsigned long long m0, m1;
    float s0, s1;
    {
        int i0 = lane, i1 = 32 + lane;
        m0 = mk[(size_t)i0*MASKW];
        m1 = mk[(size_t)i1*MASKW];
        s0 = sc[i0];
        s1 = sc[i1];
    }

    for (int ch=0; ch<MASKW; ch++) {
        unsigned long long nm0 = 0ull, nm1 = 0ull;
        float ns0 = -CUDART_INF_F, ns1 = -CUDART_INF_F;
        if (ch + 1 < MASKW) {
            int i0 = (ch+1)*64 + lane, i1 = i0 + 32;
            if (i0 < NPRE) { nm0 = mk[(size_t)i0*MASKW + ch + 1]; ns0 = sc[i0]; }
            if (i1 < NPRE) { nm1 = mk[(size_t)i1*MASKW + ch + 1]; ns1 = sc[i1]; }
        }

        unsigned inv0 = __ballot_sync(FULL, !isfinite(s0));
        unsigned inv1 = __ballot_sync(FULL, !isfinite(s1));
        unsigned long long W = (unsigned long long)inv0 | ((unsigned long long)inv1 << 32);

        int seg = ch >> 5, ln = ch & 31;
        unsigned long long rr = (seg==0) ? r0 : ((seg==1) ? r1 : r2);
        W |= __shfl_sync(FULL, rr, ln);

        unsigned long long keptb = 0ull;
        while (~W) {
            int p = __ffsll((long long)(~W)) - 1;
            keptb |= (1ull << p);
            if (lane == 0) g_kept[n*NPOST + cnt] = ch*64 + p;
            cnt++;
            if (cnt == NPOST) break;
            unsigned long long rw = __shfl_sync(FULL, (p<32) ? m0 : m1, p & 31);
            W |= rw;
        }
        if (cnt >= NPOST) break;

        unsigned long long kb = keptb;
        while (kb) {
            int p = __ffsll((long long)kb) - 1;
            kb &= kb - 1;
            size_t row = (size_t)(ch*64 + p)*MASKW;
            r0 |= mk[row + lane];
            r1 |= mk[row + 32 + lane];
            if (64 + lane < MASKW) r2 |= mk[row + 64 + lane];
        }

        m0 = nm0; m1 = nm1; s0 = ns0; s1 = ns1;
    }

    __threadfence_block();
    __syncwarp(FULL);
    for (int r = lane; r < NPOST; r += 32) {
        float4 b = make_float4(0.f,0.f,0.f,0.f);
        float vm = 0.f;
        if (r < cnt) {
            b = g_boxes[n*NPRE + g_kept[n*NPOST + r]];
            vm = 1.f;
        }
        size_t t = (size_t)n*NPOST + r;
        out[OFF_ROIS + t*4 + 0] = b.x;
        out[OFF_ROIS + t*4 + 1] = b.y;
        out[OFF_ROIS + t*4 + 2] = b.z;
        out[OFF_ROIS + t*4 + 3] = b.w;
        out[OFF_RIDX + t]  = (float)n;
        out[OFF_VMASK + t] = vm;
    }
}

// ---------------------------------------------------------------------------
// Launch
// ---------------------------------------------------------------------------
extern "C" void kernel_launch(void* const* d_in, const int* in_sizes, int n_in,
                              void* d_out, int out_size) {
    const float* x  = (const float*)d_in[0];
    const float* w  = (const float*)d_in[1];
    const float* b  = (const float*)d_in[2];
    const float* sw = (const float*)d_in[3];
    const float* sb = (const float*)d_in[4];
    const float* lw = (const float*)d_in[5];
    const float* lb = (const float*)d_in[6];
    float* out = (float*)d_out;

    cudaFuncSetAttribute(mma_conv_kernel,
                         cudaFuncAttributeMaxDynamicSharedMemorySize, SMEM_DYN);

    split_kernel<<<dim3(128, 16, 3), 256>>>(x, w);
    mma_conv_kernel<<<dim3(64, 4), CTHREADS, SMEM_DYN>>>(b, sw, lw);
    finalize_kernel<<<dim3(128, 2), 256>>>(sb, lb, d_in[7], d_in[8], out);

    void* tmp;
    uint32_t *ki, *ko;
    int *vi, *vo;
    cudaGetSymbolAddress(&tmp, g_cub_temp);
    cudaGetSymbolAddress((void**)&ki, g_key32);
    cudaGetSymbolAddress((void**)&ko, g_key32_out);
    cudaGetSymbolAddress((void**)&vi, g_val);
    cudaGetSymbolAddress((void**)&vo, g_val_out);

    {
        size_t tb = 0;
        cub::DeviceRadixSort::SortPairsDescending(nullptr, tb,
            ki, ko, vi, vo, NB*ATOT, 0, 31, (cudaStream_t)0);
        if (tb <= sizeof(g_cub_temp)) {
            cub::DeviceRadixSort::SortPairsDescending(tmp, tb,
                ki, ko, vi, vo, NB*ATOT, 0, 31, (cudaStream_t)0);
        }
    }

    gather_kernel<<<(NB*NPRE + 255)/256, 256>>>();
    mask_kernel<<<dim3(MASKW, MASKW, NB), 64>>>();
    scan_kernel<<<NB, 32>>>(out);
}

// round 15
// speedup vs baseline: 1.0659x; 1.0263x over previous
#include <cuda_runtime.h>
#include <cuda_bf16.h>
#include <cuda_fp16.h>
#include <math_constants.h>
#include <cub/cub.cuh>
#include <cstdint>

// ---------------------------------------------------------------------------
// Problem constants
// ---------------------------------------------------------------------------
#define HH 64
#define WWID 64
#define CIN 512
#define NB 2
#define NANCH 9
#define ATOT (HH*WWID*NANCH)      // 36864
#define NPRE 6000
#define NPOST 300
#define MASKW 94                  // ceil(6000/64)
#define NMS_T 0.7f

#define MTOT (NB*HH*WWID)         // 8192 pixel rows
#define KTAP 9

// Output layout (float32, concatenated in reference return order)
#define OFF_LOCS   0
#define OFF_SCORES (NB*ATOT*4)
#define OFF_ROIS   (OFF_SCORES + NB*ATOT*2)
#define OFF_RIDX   (OFF_ROIS + NB*NPOST*4)
#define OFF_ANCHOR (OFF_RIDX + NB*NPOST)
#define OFF_VMASK  (OFF_ANCHOR + ATOT*4)

#define APLSZ ((size_t)MTOT*CIN)        // elements per A fp16 plane
#define BPLSZ ((size_t)KTAP*CIN*CIN)    // elements per B fp16 plane
#define BSCALE 64.0f
#define BUNSCALE 0.015625f
#define NQ 4                             // heads channel-split = conv N-tiles

// ---------------------------------------------------------------------------
// Scratch
// ---------------------------------------------------------------------------
__device__ __half g_axh[2*APLSZ];                // input fp16 planes (NHWC)
__device__ __half g_bxh[2*BPLSZ];                // weight planes [tap][k][c], x64
__device__ float g_part[(size_t)NQ*NB*56*4096]; // heads partials [q][n][o][pix]
__device__ float g_score[NB*ATOT];
__device__ uint32_t g_key32[NB*ATOT];
__device__ uint32_t g_key32_out[NB*ATOT];
__device__ int   g_val[NB*ATOT];
__device__ int   g_val_out[NB*ATOT];
__device__ float4 g_roi[NB*ATOT];
__device__ float4 g_boxes[NB*NPRE];
__device__ float g_boxsc[NB*NPRE];
__device__ unsigned long long g_mask[(size_t)NB*NPRE*MASKW];
__device__ int g_kept[NB*NPOST];
__device__ __align__(256) unsigned char g_cub_temp[8<<20];

// ---------------------------------------------------------------------------
// PTX helpers
// ---------------------------------------------------------------------------
__device__ __forceinline__ uint32_t smem_u32(const void* p) {
    uint32_t a;
    asm("{ .reg .u64 t; cvta.to.shared.u64 t, %1; cvt.u32.u64 %0, t; }" : "=r"(a) : "l"(p));
    return a;
}
__device__ __forceinline__ void cp16(uint32_t dst, const void* src, int srcsize) {
    asm volatile("cp.async.cg.shared.global [%0], [%1], 16, %2;"
                 :: "r"(dst), "l"(src), "r"(srcsize) : "memory");
}
__device__ __forceinline__ void cp_commit() { asm volatile("cp.async.commit_group;" ::: "memory"); }
template<int N> __device__ __forceinline__ void cp_wait() {
    asm volatile("cp.async.wait_group %0;" :: "n"(N) : "memory");
}

#define LDSM4(r0, r1, r2, r3, a) \
    asm volatile("ldmatrix.sync.aligned.m8n8.x4.shared.b16 {%0,%1,%2,%3}, [%4];" \
                 : "=r"(r0), "=r"(r1), "=r"(r2), "=r"(r3) : "r"(a))

// fp16 2-way split
__device__ __forceinline__ void f16split(float v, __half& o0, __half& o1) {
    __half h0 = __float2half_rn(v);
    float r = v - __half2float(h0);
    o0 = h0;
    o1 = __float2half_rn(r);
}

#define MMA_F16(d, a, b) \
    asm volatile("mma.sync.aligned.m16n8k16.row.col.f32.f16.f16.f32 " \
                 "{%0,%1,%2,%3},{%4,%5,%6,%7},{%8,%9},{%0,%1,%2,%3};" \
                 : "+f"((d)[0]), "+f"((d)[1]), "+f"((d)[2]), "+f"((d)[3]) \
                 : "r"((a)[0]), "r"((a)[1]), "r"((a)[2]), "r"((a)[3]), \
                   "r"((b)[0]), "r"((b)[1]))

#define MMA_F16_ZC(d, a, b, z) \
    asm volatile("mma.sync.aligned.m16n8k16.row.col.f32.f16.f16.f32 " \
                 "{%0,%1,%2,%3},{%4,%5,%6,%7},{%8,%9},{%10,%10,%10,%10};" \
                 : "=f"((d)[0]), "=f"((d)[1]), "=f"((d)[2]), "=f"((d)[3]) \
                 : "r"((a)[0]), "r"((a)[1]), "r"((a)[2]), "r"((a)[3]), \
                   "r"((b)[0]), "r"((b)[1]), "f"(z))

// ---------------------------------------------------------------------------
// Combined input/weight split. grid (128, 16, 3).
// ---------------------------------------------------------------------------
__global__ void split_kernel(const float* __restrict__ x, const float* __restrict__ w) {
    if (blockIdx.z < 2) {
        __shared__ float tile[32][33];
        int pt = blockIdx.x, ct = blockIdx.y, n = blockIdx.z;
        int tx = threadIdx.x & 31, ty = threadIdx.x >> 5;
#pragma unroll
        for (int r = 0; r < 4; r++) {
            int c = ct*32 + ty + r*8;
            int p = pt*32 + tx;
            tile[ty + r*8][tx] = x[((size_t)(n*CIN + c))*4096 + p];
        }
        __syncthreads();
        int cl = (threadIdx.x & 15)*2;
        int pl0 = threadIdx.x >> 4;
#pragma unroll
        for (int r = 0; r < 2; r++) {
            int pl = pl0 + r*16;
            int pg = pt*32 + pl;
            int cg = ct*32 + cl;
            float a0 = tile[cl][pl];
            float a1 = tile[cl+1][pl];
            __half h00, h01, h10, h11;
            f16split(a0, h00, h01);
            f16split(a1, h10, h11);
            size_t o = ((size_t)(n*4096 + pg))*CIN + cg;
            *(__half2*)&g_axh[o] = __halves2half2(h00, h10);
            *(__half2*)&g_axh[APLSZ + o] = __halves2half2(h01, h11);
        }
    } else {
        int base = (blockIdx.y*128 + blockIdx.x)*256 + threadIdx.x;
        for (int e = base; e < KTAP*CIN*CIN; e += 128*16*256) {
            int c = e & 511;
            int k = (e >> 9) & 511;
            int tap = e >> 18;
            float v = w[((size_t)k*CIN + c)*KTAP + tap] * BSCALE;
            __half h0, h1;
            f16split(v, h0, h1);
            g_bxh[e] = h0;
            g_bxh[BPLSZ + e] = h1;
        }
    }
}

// ---------------------------------------------------------------------------
// fp16x3 emulated-fp32 conv GEMM, cin-major / tap-minor (A-band reuse).
// Block tile M=128 x N=128; grid (64, 4). 256 threads, 8 warps.
// MMA products issued in three passes (hh, hl, lh) across all 16 accumulators
// -> no adjacent same-accumulator RAW chains. Per-acc op order unchanged
// (hh then hl then lh) => bit-identical numerics to round 12.
// ---------------------------------------------------------------------------
#define A_PLANE 21120
#define A_BUF   42240
#define B_BASE  84480
#define B_SLOT  20480
#define B_PLANE 10240
#define SMEM_DYN 145920
#define HSTRIDE 132

__device__ __forceinline__ void load_a(int cc, int parity, uint32_t sb,
                                       int n, int y0, int tid) {
    int c0 = cc*32;
    for (int e = tid; e < 2112; e += 256) {
        int seg = e & 3;
        int plane = (e >> 2) & 1;
        int entry = e >> 3;
        int col = entry % 66;
        int dy  = entry / 66;
        int y = y0 - 1 + dy;
        int x = col - 1;
        bool valid = ((unsigned)y < 64u) && ((unsigned)x < 64u);
        const __half* src = valid ?
            g_axh + (size_t)plane*APLSZ + ((size_t)(n*4096 + y*64 + x))*CIN + c0 + seg*8
            : g_axh;
        uint32_t dst = sb + parity*A_BUF + plane*A_PLANE + entry*80 + seg*16;
        cp16(dst, src, valid ? 16 : 0);
    }
}

__device__ __forceinline__ void load_b(int s, uint32_t sb, int k0, int tid) {
    int cc = s/9, tap = s - cc*9;
    int c0 = cc*32;
    int slot = s % 3;
#pragma unroll
    for (int r = 0; r < 4; r++) {
        int i = r*256 + tid;
        int plane = i >> 9;
        int rs = i & 511;
        int row = rs >> 2, seg = rs & 3;
        const __half* src = g_bxh + (size_t)plane*BPLSZ +
            ((size_t)tap*CIN + k0 + row)*CIN + c0 + seg*8;
        uint32_t dst = sb + B_BASE + slot*B_SLOT + plane*B_PLANE + row*80 + seg*16;
        cp16(dst, src, 16);
    }
}

__global__ void __launch_bounds__(256) mma_conv_kernel(const float* __restrict__ bias,
                                                       const float* __restrict__ sw,
                                                       const float* __restrict__ lw) {
    extern __shared__ char smem[];
    uint32_t sb = smem_u32(smem);
    int tid = threadIdx.x;
    int lane = tid & 31, w = tid >> 5;
    int wm = w & 3, wn = w >> 2;
    int g = lane >> 2, t = lane & 3;

    int q  = blockIdx.y;
    int p0 = blockIdx.x * 128;
    int n  = p0 >> 12;
    int y0 = (p0 & 4095) >> 6;
    int k0 = q * 128;

    int y_base = wm >> 1;
    int x_base = (wm & 1)*32 + ((lane>>3)&1)*8 + (lane&7);
    uint32_t aoff0 = (uint32_t)((y_base*66 + x_base)*80 + (lane>>4)*16);
    uint32_t boff0 = (uint32_t)((wn*64 + ((lane>>4)&1)*8 + (lane&7))*80 + ((lane>>3)&1)*16);

    float run[2][8][4];
    float acc[2][8][4];
#pragma unroll
    for (int mt=0; mt<2; mt++)
#pragma unroll
        for (int nt=0; nt<8; nt++)
#pragma unroll
            for (int j=0; j<4; j++) run[mt][nt][j] = 0.f;

    float fz = 0.0f;

    load_a(0, 0, sb, n, y0, tid); cp_commit();
    load_b(0, sb, k0, tid);       cp_commit();
    load_b(1, sb, k0, tid);       cp_commit();

    for (int s = 0; s < 144; s++) {
        int cc = s/9, tap = s - cc*9;
        if (s + 2 < 144) load_b(s+2, sb, k0, tid);
        if (tap == 7 && cc < 15) load_a(cc+1, (cc+1)&1, sb, n, y0, tid);
        cp_commit();
        cp_wait<2>();
        __syncthreads();

        int dy = tap/3, dx = tap - dy*3;
        uint32_t abase = sb + (cc&1)*A_BUF + aoff0 + (uint32_t)((dy*66 + dx)*80);
        uint32_t bbase = sb + B_BASE + (s%3)*B_SLOT + boff0;

#pragma unroll
        for (int ks = 0; ks < 2; ks++) {
            uint32_t kof = (uint32_t)(ks*32);
            uint32_t aH = abase + kof;
            uint32_t aL = aH + A_PLANE;
            uint32_t bH = bbase + kof;
            uint32_t bL = bH + B_PLANE;

            uint32_t ah[2][4], al[2][4], bh[8][2], bl[8][2];
            LDSM4(ah[0][0], ah[0][1], ah[0][2], ah[0][3], aH);
            LDSM4(ah[1][0], ah[1][1], ah[1][2], ah[1][3], aH + 1280);
            LDSM4(al[0][0], al[0][1], al[0][2], al[0][3], aL);
            LDSM4(al[1][0], al[1][1], al[1][2], al[1][3], aL + 1280);
            LDSM4(bh[0][0], bh[0][1], bh[1][0], bh[1][1], bH);
            LDSM4(bh[2][0], bh[2][1], bh[3][0], bh[3][1], bH + 1280);
            LDSM4(bh[4][0], bh[4][1], bh[5][0], bh[5][1], bH + 2560);
            LDSM4(bh[6][0], bh[6][1], bh[7][0], bh[7][1], bH + 3840);
            LDSM4(bl[0][0], bl[0][1], bl[1][0], bl[1][1], bL);
            LDSM4(bl[2][0], bl[2][1], bl[3][0], bl[3][1], bL + 1280);
            LDSM4(bl[4][0], bl[4][1], bl[5][0], bl[5][1], bL + 2560);
            LDSM4(bl[6][0], bl[6][1], bl[7][0], bl[7][1], bL + 3840);

            bool zc = (ks == 0) && (tap == 0 || tap == 3 || tap == 6);
            // Pass 1: hh across all accumulators (starts/continues windows)
            if (zc) {
#pragma unroll
                for (int mt = 0; mt < 2; mt++)
#pragma unroll
                    for (int nt = 0; nt < 8; nt++)
                        MMA_F16_ZC(acc[mt][nt], ah[mt], bh[nt], fz);
            } else {
#pragma unroll
                for (int mt = 0; mt < 2; mt++)
#pragma unroll
                    for (int nt = 0; nt < 8; nt++)
                        MMA_F16(acc[mt][nt], ah[mt], bh[nt]);
            }
            // Pass 2: hl
#pragma unroll
            for (int mt = 0; mt < 2; mt++)
#pragma unroll
                for (int nt = 0; nt < 8; nt++)
                    MMA_F16(acc[mt][nt], ah[mt], bl[nt]);
            // Pass 3: lh
#pragma unroll
            for (int mt = 0; mt < 2; mt++)
#pragma unroll
                for (int nt = 0; nt < 8; nt++)
                    MMA_F16(acc[mt][nt], al[mt], bh[nt]);
        }
        if (tap == 2 || tap == 5 || tap == 8) {
#pragma unroll
            for (int mt = 0; mt < 2; mt++)
#pragma unroll
                for (int nt = 0; nt < 8; nt++)
#pragma unroll
                    for (int j = 0; j < 4; j++)
                        run[mt][nt][j] += acc[mt][nt][j];
        }
        __syncthreads();
    }

    // ---- Fused epilogue ----
    float* hbuf = (float*)smem;                       // [128][HSTRIDE]
    float* w2   = (float*)(smem + 128*HSTRIDE*4);     // [54][128]

#pragma unroll
    for (int mt = 0; mt < 2; mt++) {
        int lr0 = wm*32 + mt*16 + g;
#pragma unroll
        for (int nt = 0; nt < 8; nt++) {
            int lch = wn*64 + nt*8 + t*2;
            int ch = k0 + lch;
            float b0 = bias[ch], b1 = bias[ch+1];
            hbuf[lr0*HSTRIDE + lch]     = fmaxf(fmaf(run[mt][nt][0], BUNSCALE, b0), 0.f);
            hbuf[lr0*HSTRIDE + lch + 1] = fmaxf(fmaf(run[mt][nt][1], BUNSCALE, b1), 0.f);
            hbuf[(lr0+8)*HSTRIDE + lch]     = fmaxf(fmaf(run[mt][nt][2], BUNSCALE, b0), 0.f);
            hbuf[(lr0+8)*HSTRIDE + lch + 1] = fmaxf(fmaf(run[mt][nt][3], BUNSCALE, b1), 0.f);
        }
    }
    for (int e = tid; e < 54*128; e += 256) {
        int o = e >> 7, cc = e & 127;
        w2[o*128 + cc] = (o < 18) ? sw[o*CIN + k0 + cc] : lw[(o-18)*CIN + k0 + cc];
    }
    __syncthreads();

    int px0 = tid & 63, og = tid >> 6;
#pragma unroll
    for (int half = 0; half < 2; half++) {
        int px = half*64 + px0;
        float hacc[14];
#pragma unroll
        for (int t14 = 0; t14 < 14; t14++) hacc[t14] = 0.f;
#pragma unroll 2
        for (int cc4 = 0; cc4 < 32; cc4++) {
            float4 hv = *(const float4*)&hbuf[px*HSTRIDE + cc4*4];
#pragma unroll
            for (int t14 = 0; t14 < 14; t14++) {
                int o = og + 4*t14;
                if (o < 54) {
                    float4 wv = *(const float4*)&w2[o*128 + cc4*4];
                    hacc[t14] = fmaf(wv.x, hv.x, hacc[t14]);
                    hacc[t14] = fmaf(wv.y, hv.y, hacc[t14]);
                    hacc[t14] = fmaf(wv.z, hv.z, hacc[t14]);
                    hacc[t14] = fmaf(wv.w, hv.w, hacc[t14]);
                }
            }
        }
        int pix = (p0 & 4095) + px;
#pragma unroll
        for (int t14 = 0; t14 < 14; t14++) {
            int o = og + 4*t14;
            if (o < 54)
                g_part[((size_t)((q*2+n)*56 + o))*4096 + pix] = hacc[t14];
        }
    }
}

// ---------------------------------------------------------------------------
// Anchor
// ---------------------------------------------------------------------------
__device__ __forceinline__ void anchor_calc(int y, int x, int k,
                                            float& o0, float& o1, float& o2, float& o3) {
    const double ratios[3] = {0.5, 1.0, 2.0};
    const double scales[3] = {8.0, 16.0, 32.0};
    int i = k/3, j = k%3;
    double h = 16.0*scales[j]*sqrt(ratios[i]);
    double w = 16.0*scales[j]*sqrt(1.0/ratios[i]);
    float b0 = (float)(8.0 - h*0.5);
    float b1 = (float)(8.0 - w*0.5);
    float b2 = (float)(8.0 + h*0.5);
    float b3 = (float)(8.0 + w*0.5);
    o0 = (float)((double)b0 + (double)(y*16));
    o1 = (float)((double)b1 + (double)(x*16));
    o2 = (float)((double)b2 + (double)(y*16));
    o3 = (float)((double)b3 + (double)(x*16));
}

__device__ __forceinline__ float load_dim(const void* p) {
    int iv = *(const int*)p;
    if (iv > 0 && iv < (1<<20)) return (float)iv;
    return *(const float*)p;
}

// ---------------------------------------------------------------------------
// Finalize. grid (128, 2): 32-pixel blocks.
// ---------------------------------------------------------------------------
__global__ __launch_bounds__(256) void finalize_kernel(const float* __restrict__ sb,
                                                       const float* __restrict__ lb,
                                                       const void* ihp, const void* iwp,
                                                       float* __restrict__ out) {
    __shared__ float s_o[54][32];
    int blk = blockIdx.x;
    int y = blk >> 1;
    int ph = (blk & 1) * 32;
    int n = blockIdx.y;
    int tid = threadIdx.x;

    for (int e=tid; e<1728; e+=256) {
        int px = e & 31, o = e >> 5;
        size_t base = (size_t)y*64 + ph + px;
        float s = 0.f;
#pragma unroll
        for (int q = 0; q < NQ; q++)
            s += g_part[((size_t)((q*2+n)*56 + o))*4096 + base];
        s += (o<18) ? sb[o] : lb[o-18];
        s_o[o][px] = s;
        int pix = y*64 + ph + px;
        if (o < 18)
            out[OFF_SCORES + ((size_t)n*ATOT + (size_t)pix*9 + (o>>1))*2 + (o&1)] = s;
        else {
            int c = o-18;
            out[OFF_LOCS + ((size_t)n*ATOT + (size_t)pix*9 + (c>>2))*4 + (c&3)] = s;
        }
    }
    __syncthreads();

    float img_h = load_dim(ihp), img_w = load_dim(iwp);

    for (int e=tid; e<288; e+=256) {
        int p2 = e & 31;
        int k  = e >> 5;
        float s0 = s_o[2*k][p2], s1 = s_o[2*k+1][p2];
        float m  = fmaxf(s0,s1);
        float e0 = expf(s0-m), e1 = expf(s1-m);
        float fg = e1/(e0+e1);

        float d0 = s_o[18+4*k+0][p2];
        float d1 = s_o[18+4*k+1][p2];
        float d2 = s_o[18+4*k+2][p2];
        float d3 = s_o[18+4*k+3][p2];

        int xcol = ph + p2;
        float a0,a1,a2,a3;
        anchor_calc(y, xcol, k, a0,a1,a2,a3);

        float ah = a2-a0, aw = a3-a1;
        float acy = a0 + 0.5f*ah, acx = a1 + 0.5f*aw;
        float cy = fmaf(d0, ah, acy);
        float cx = fmaf(d1, aw, acx);
        float h  = expf(d2)*ah;
        float w  = expf(d3)*aw;
        float r0 = fminf(fmaxf(cy-0.5f*h, 0.f), img_h);
        float r1 = fminf(fmaxf(cx-0.5f*w, 0.f), img_w);
        float r2 = fminf(fmaxf(cy+0.5f*h, 0.f), img_h);
        float r3 = fminf(fmaxf(cx+0.5f*w, 0.f), img_w);
        bool valid = (r2-r0 >= 16.f) && (r3-r1 >= 16.f);

        int aidx = (y*64 + xcol)*9 + k;
        int gi = n*ATOT + aidx;
        float sc = valid ? fg : -CUDART_INF_F;
        g_score[gi] = sc;
        g_roi[gi] = make_float4(r0,r1,r2,r3);
        uint32_t u = valid ? __float_as_uint(fg) : 0u;
        g_key32[gi] = u | ((uint32_t)(1 - n) << 30);
        g_val[gi] = gi;
        if (n == 0) {
            out[OFF_ANCHOR + (size_t)aidx*4 + 0] = a0;
            out[OFF_ANCHOR + (size_t)aidx*4 + 1] = a1;
            out[OFF_ANCHOR + (size_t)aidx*4 + 2] = a2;
            out[OFF_ANCHOR + (size_t)aidx*4 + 3] = a3;
        }
    }
}

// ---------------------------------------------------------------------------
// Gather top-6000 boxes + scores after sort
// ---------------------------------------------------------------------------
__global__ void gather_kernel() {
    int t = blockIdx.x*256 + threadIdx.x;
    if (t >= NB*NPRE) return;
    int n = t/NPRE, i = t%NPRE;
    int gi = g_val_out[n*ATOT + i];
    g_boxes[t] = g_roi[gi];
    g_boxsc[t] = g_score[gi];
}

// ---------------------------------------------------------------------------
// NMS bitmask (upper triangle jb >= ib only)
// ---------------------------------------------------------------------------
__global__ __launch_bounds__(64) void mask_kernel() {
    int n  = blockIdx.z;
    int jb = blockIdx.x;
    int ib = blockIdx.y;
    if (jb < ib) return;
    int t  = threadIdx.x;

    __shared__ float4 cb[64];
    int j = jb*64 + t;
    cb[t] = (j < NPRE) ? g_boxes[n*NPRE + j] : make_float4(0.f,0.f,0.f,0.f);
    __syncthreads();

    int i = ib*64 + t;
    if (i >= NPRE) return;
    float4 bi = g_boxes[n*NPRE + i];
    float areai = (bi.z-bi.x)*(bi.w-bi.y);

    unsigned long long word = 0ull;
    int jmax = min(64, NPRE - jb*64);
    for (int jj=0; jj<jmax; jj++) {
        float4 bj = cb[jj];
        float areaj = (bj.z-bj.x)*(bj.w-bj.y);
        float ih = fmaxf(fminf(bi.z,bj.z) - fmaxf(bi.x,bj.x), 0.f);
        float iw = fmaxf(fminf(bi.w,bj.w) - fmaxf(bi.y,bj.y), 0.f);
        float inter = ih*iw;
        float iou = inter/(areai + areaj - inter + 1e-9f);
        if (iou > NMS_T) word |= (1ull << jj);
    }
    g_mask[((size_t)n*NPRE + i)*MASKW + jb] = word;
}

// ---------------------------------------------------------------------------
// Greedy NMS scan + fused output
// ---------------------------------------------------------------------------
__global__ void scan_kernel(float* __restrict__ out) {
    int n = blockIdx.x;
    int lane = threadIdx.x;
    const unsigned FULL = 0xffffffffu;

    unsigned long long r0=0ull, r1=0ull, r2=0ull;
    int cnt = 0;
    const unsigned long long* mk = g_mask + (size_t)n*NPRE*MASKW;
    const float* sc = g_boxsc + n*NPRE;

    unsigned long long m0, m1;
    float s0, s1;
    {
        int i0 = lane, i1 = 32 + lane;
        m0 = mk[(size_t)i0*MASKW];
        m1 = mk[(size_t)i1*MASKW];
        s0 = sc[i0];
        s1 = sc[i1];
    }

    for (int ch=0; ch<MASKW; ch++) {
        unsigned long long nm0 = 0ull, nm1 = 0ull;
        float ns0 = -CUDART_INF_F, ns1 = -CUDART_INF_F;
        if (ch + 1 < MASKW) {
            int i0 = (ch+1)*64 + lane, i1 = i0 + 32;
            if (i0 < NPRE) { nm0 = mk[(size_t)i0*MASKW + ch + 1]; ns0 = sc[i0]; }
            if (i1 < NPRE) { nm1 = mk[(size_t)i1*MASKW + ch + 1]; ns1 = sc[i1]; }
        }

        unsigned inv0 = __ballot_sync(FULL, !isfinite(s0));
        unsigned inv1 = __ballot_sync(FULL, !isfinite(s1));
        unsigned long long W = (unsigned long long)inv0 | ((unsigned long long)inv1 << 32);

        int seg = ch >> 5, ln = ch & 31;
        unsigned long long rr = (seg==0) ? r0 : ((seg==1) ? r1 : r2);
        W |= __shfl_sync(FULL, rr, ln);

        unsigned long long keptb = 0ull;
        while (~W) {
            int p = __ffsll((long long)(~W)) - 1;
            keptb |= (1ull << p);
            if (lane == 0) g_kept[n*NPOST + cnt] = ch*64 + p;
            cnt++;
            if (cnt == NPOST) break;
            unsigned long long rw = __shfl_sync(FULL, (p<32) ? m0 : m1, p & 31);
            W |= rw;
        }
        if (cnt >= NPOST) break;

        unsigned long long kb = keptb;
        while (kb) {
            int p = __ffsll((long long)kb) - 1;
            kb &= kb - 1;
            size_t row = (size_t)(ch*64 + p)*MASKW;
            r0 |= mk[row + lane];
            r1 |= mk[row + 32 + lane];
            if (64 + lane < MASKW) r2 |= mk[row + 64 + lane];
        }

        m0 = nm0; m1 = nm1; s0 = ns0; s1 = ns1;
    }

    __threadfence_block();
    __syncwarp(FULL);
    for (int r = lane; r < NPOST; r += 32) {
        float4 b = make_float4(0.f,0.f,0.f,0.f);
        float vm = 0.f;
        if (r < cnt) {
            b = g_boxes[n*NPRE + g_kept[n*NPOST + r]];
            vm = 1.f;
        }
        size_t t = (size_t)n*NPOST + r;
        out[OFF_ROIS + t*4 + 0] = b.x;
        out[OFF_ROIS + t*4 + 1] = b.y;
        out[OFF_ROIS + t*4 + 2] = b.z;
        out[OFF_ROIS + t*4 + 3] = b.w;
        out[OFF_RIDX + t]  = (float)n;
        out[OFF_VMASK + t] = vm;
    }
}

// ---------------------------------------------------------------------------
// Launch
// ---------------------------------------------------------------------------
extern "C" void kernel_launch(void* const* d_in, const int* in_sizes, int n_in,
                              void* d_out, int out_size) {
    const float* x  = (const float*)d_in[0];
    const float* w  = (const float*)d_in[1];
    const float* b  = (const float*)d_in[2];
    const float* sw = (const float*)d_in[3];
    const float* sb = (const float*)d_in[4];
    const float* lw = (const float*)d_in[5];
    const float* lb = (const float*)d_in[6];
    float* out = (float*)d_out;

    cudaFuncSetAttribute(mma_conv_kernel,
                         cudaFuncAttributeMaxDynamicSharedMemorySize, SMEM_DYN);

    split_kernel<<<dim3(128, 16, 3), 256>>>(x, w);
    mma_conv_kernel<<<dim3(64, 4), 256, SMEM_DYN>>>(b, sw, lw);
    finalize_kernel<<<dim3(128, 2), 256>>>(sb, lb, d_in[7], d_in[8], out);

    void* tmp;
    uint32_t *ki, *ko;
    int *vi, *vo;
    cudaGetSymbolAddress(&tmp, g_cub_temp);
    cudaGetSymbolAddress((void**)&ki, g_key32);
    cudaGetSymbolAddress((void**)&ko, g_key32_out);
    cudaGetSymbolAddress((void**)&vi, g_val);
    cudaGetSymbolAddress((void**)&vo, g_val_out);

    {
        size_t tb = 0;
        cub::DeviceRadixSort::SortPairsDescending(nullptr, tb,
            ki, ko, vi, vo, NB*ATOT, 0, 31, (cudaStream_t)0);
        if (tb <= sizeof(g_cub_temp)) {
            cub::DeviceRadixSort::SortPairsDescending(tmp, tb,
                ki, ko, vi, vo, NB*ATOT, 0, 31, (cudaStream_t)0);
        }
    }

    gather_kernel<<<(NB*NPRE + 255)/256, 256>>>();
    mask_kernel<<<dim3(MASKW, MASKW, NB), 64>>>();
    scan_kernel<<<NB, 32>>>(out);
}

// round 16
// speedup vs baseline: 1.1628x; 1.0909x over previous
#include <cuda_runtime.h>
#include <cuda_bf16.h>
#include <cuda_fp16.h>
#include <math_constants.h>
#include <cub/cub.cuh>
#include <cstdint>

// ---------------------------------------------------------------------------
// Problem constants
// ---------------------------------------------------------------------------
#define HH 64
#define WWID 64
#define CIN 512
#define NB 2
#define NANCH 9
#define ATOT (HH*WWID*NANCH)      // 36864
#define NPRE 6000
#define NPOST 300
#define MASKW 94                  // ceil(6000/64)
#define NMS_T 0.7f

#define MTOT (NB*HH*WWID)         // 8192 pixel rows
#define KTAP 9

// Output layout (float32, concatenated in reference return order)
#define OFF_LOCS   0
#define OFF_SCORES (NB*ATOT*4)
#define OFF_ROIS   (OFF_SCORES + NB*ATOT*2)
#define OFF_RIDX   (OFF_ROIS + NB*NPOST*4)
#define OFF_ANCHOR (OFF_RIDX + NB*NPOST)
#define OFF_VMASK  (OFF_ANCHOR + ATOT*4)

#define APLSZ ((size_t)MTOT*CIN)        // elements per A fp16 plane
#define BPLSZ ((size_t)KTAP*CIN*CIN)    // elements per B fp16 plane
#define BSCALE 64.0f
#define BUNSCALE 0.015625f
#define NQ 4                             // heads channel-split = conv N-tiles

// ---------------------------------------------------------------------------
// Scratch
// ---------------------------------------------------------------------------
__device__ __half g_axh[2*APLSZ];                // input fp16 planes (NHWC)
__device__ __half g_bxh[2*BPLSZ];                // weight planes [tap][k][c], x64
__device__ float g_part[(size_t)NQ*NB*56*4096]; // heads partials [q][n][o][pix]
__device__ float g_score[NB*ATOT];
__device__ uint32_t g_key32[NB*ATOT];
__device__ uint32_t g_key32_out[NB*ATOT];
__device__ int   g_val[NB*ATOT];
__device__ int   g_val_out[NB*ATOT];
__device__ float4 g_roi[NB*ATOT];
__device__ float4 g_boxes[NB*NPRE];
__device__ float g_boxsc[NB*NPRE];
__device__ unsigned long long g_mask[(size_t)NB*NPRE*MASKW];
__device__ int g_kept[NB*NPOST];
__device__ __align__(256) unsigned char g_cub_temp[8<<20];

// ---------------------------------------------------------------------------
// PTX helpers
// ---------------------------------------------------------------------------
__device__ __forceinline__ uint32_t smem_u32(const void* p) {
    uint32_t a;
    asm("{ .reg .u64 t; cvta.to.shared.u64 t, %1; cvt.u32.u64 %0, t; }" : "=r"(a) : "l"(p));
    return a;
}
__device__ __forceinline__ void cp16(uint32_t dst, const void* src, int srcsize) {
    asm volatile("cp.async.cg.shared.global [%0], [%1], 16, %2;"
                 :: "r"(dst), "l"(src), "r"(srcsize) : "memory");
}
__device__ __forceinline__ void cp_commit() { asm volatile("cp.async.commit_group;" ::: "memory"); }
template<int N> __device__ __forceinline__ void cp_wait() {
    asm volatile("cp.async.wait_group %0;" :: "n"(N) : "memory");
}

#define LDSM4(r0, r1, r2, r3, a) \
    asm volatile("ldmatrix.sync.aligned.m8n8.x4.shared.b16 {%0,%1,%2,%3}, [%4];" \
                 : "=r"(r0), "=r"(r1), "=r"(r2), "=r"(r3) : "r"(a))

// fp16 2-way split
__device__ __forceinline__ void f16split(float v, __half& o0, __half& o1) {
    __half h0 = __float2half_rn(v);
    float r = v - __half2float(h0);
    o0 = h0;
    o1 = __float2half_rn(r);
}

#define MMA_F16(d, a, b) \
    asm volatile("mma.sync.aligned.m16n8k16.row.col.f32.f16.f16.f32 " \
                 "{%0,%1,%2,%3},{%4,%5,%6,%7},{%8,%9},{%0,%1,%2,%3};" \
                 : "+f"((d)[0]), "+f"((d)[1]), "+f"((d)[2]), "+f"((d)[3]) \
                 : "r"((a)[0]), "r"((a)[1]), "r"((a)[2]), "r"((a)[3]), \
                   "r"((b)[0]), "r"((b)[1]))

#define MMA_F16_ZC(d, a, b, z) \
    asm volatile("mma.sync.aligned.m16n8k16.row.col.f32.f16.f16.f32 " \
                 "{%0,%1,%2,%3},{%4,%5,%6,%7},{%8,%9},{%10,%10,%10,%10};" \
                 : "=f"((d)[0]), "=f"((d)[1]), "=f"((d)[2]), "=f"((d)[3]) \
                 : "r"((a)[0]), "r"((a)[1]), "r"((a)[2]), "r"((a)[3]), \
                   "r"((b)[0]), "r"((b)[1]), "f"(z))

// ---------------------------------------------------------------------------
// Combined input/weight split. grid (128, 16, 3).
// ---------------------------------------------------------------------------
__global__ void split_kernel(const float* __restrict__ x, const float* __restrict__ w) {
    if (blockIdx.z < 2) {
        __shared__ float tile[32][33];
        int pt = blockIdx.x, ct = blockIdx.y, n = blockIdx.z;
        int tx = threadIdx.x & 31, ty = threadIdx.x >> 5;
#pragma unroll
        for (int r = 0; r < 4; r++) {
            int c = ct*32 + ty + r*8;
            int p = pt*32 + tx;
            tile[ty + r*8][tx] = x[((size_t)(n*CIN + c))*4096 + p];
        }
        __syncthreads();
        int cl = (threadIdx.x & 15)*2;
        int pl0 = threadIdx.x >> 4;
#pragma unroll
        for (int r = 0; r < 2; r++) {
            int pl = pl0 + r*16;
            int pg = pt*32 + pl;
            int cg = ct*32 + cl;
            float a0 = tile[cl][pl];
            float a1 = tile[cl+1][pl];
            __half h00, h01, h10, h11;
            f16split(a0, h00, h01);
            f16split(a1, h10, h11);
            size_t o = ((size_t)(n*4096 + pg))*CIN + cg;
            *(__half2*)&g_axh[o] = __halves2half2(h00, h10);
            *(__half2*)&g_axh[APLSZ + o] = __halves2half2(h01, h11);
        }
    } else {
        int base = (blockIdx.y*128 + blockIdx.x)*256 + threadIdx.x;
        for (int e = base; e < KTAP*CIN*CIN; e += 128*16*256) {
            int c = e & 511;
            int k = (e >> 9) & 511;
            int tap = e >> 18;
            float v = w[((size_t)k*CIN + c)*KTAP + tap] * BSCALE;
            __half h0, h1;
            f16split(v, h0, h1);
            g_bxh[e] = h0;
            g_bxh[BPLSZ + e] = h1;
        }
    }
}

// ---------------------------------------------------------------------------
// fp16x3 emulated-fp32 conv GEMM: 48 macro-steps of 3 taps (one window) each.
// Block tile M=128 x N=128; grid (64, 4). 256 threads, 8 warps.
// B ring: 6 slots (3 consumed/step, 3 in flight, 1-step lookahead wait<1>).
// Barriers: 96 total (2/step x 48) vs 288 before. Numerics bit-identical
// (same windows, same per-window op order).
// ---------------------------------------------------------------------------
#define A_PLANE 21120
#define A_BUF   42240
#define B_BASE  84480
#define B_SLOT  20480
#define B_PLANE 10240
#define SMEM_DYN 207360          // 2*A_BUF + 6*B_SLOT
#define HSTRIDE 132

__device__ __forceinline__ void load_a(int cc, int parity, uint32_t sb,
                                       int n, int y0, int tid) {
    int c0 = cc*32;
    for (int e = tid; e < 2112; e += 256) {
        int seg = e & 3;
        int plane = (e >> 2) & 1;
        int entry = e >> 3;
        int col = entry % 66;
        int dy  = entry / 66;
        int y = y0 - 1 + dy;
        int x = col - 1;
        bool valid = ((unsigned)y < 64u) && ((unsigned)x < 64u);
        const __half* src = valid ?
            g_axh + (size_t)plane*APLSZ + ((size_t)(n*4096 + y*64 + x))*CIN + c0 + seg*8
            : g_axh;
        uint32_t dst = sb + parity*A_BUF + plane*A_PLANE + entry*80 + seg*16;
        cp16(dst, src, valid ? 16 : 0);
    }
}

// B chunk c (0..143): cc = c/9, tap = c%9, ring slot = c%6
__device__ __forceinline__ void load_b(int c, uint32_t sb, int k0, int tid) {
    int cc = c/9, tap = c - cc*9;
    int c0 = cc*32;
    int slot = c % 6;
#pragma unroll
    for (int r = 0; r < 4; r++) {
        int i = r*256 + tid;
        int plane = i >> 9;
        int rs = i & 511;
        int row = rs >> 2, seg = rs & 3;
        const __half* src = g_bxh + (size_t)plane*BPLSZ +
            ((size_t)tap*CIN + k0 + row)*CIN + c0 + seg*8;
        uint32_t dst = sb + B_BASE + slot*B_SLOT + plane*B_PLANE + row*80 + seg*16;
        cp16(dst, src, 16);
    }
}

__global__ void __launch_bounds__(256) mma_conv_kernel(const float* __restrict__ bias,
                                                       const float* __restrict__ sw,
                                                       const float* __restrict__ lw) {
    extern __shared__ char smem[];
    uint32_t sb = smem_u32(smem);
    int tid = threadIdx.x;
    int lane = tid & 31, w = tid >> 5;
    int wm = w & 3, wn = w >> 2;
    int g = lane >> 2, t = lane & 3;

    int q  = blockIdx.y;
    int p0 = blockIdx.x * 128;
    int n  = p0 >> 12;
    int y0 = (p0 & 4095) >> 6;
    int k0 = q * 128;

    int y_base = wm >> 1;
    int x_base = (wm & 1)*32 + ((lane>>3)&1)*8 + (lane&7);
    uint32_t aoff0 = (uint32_t)((y_base*66 + x_base)*80 + (lane>>4)*16);
    uint32_t boff0 = (uint32_t)((wn*64 + ((lane>>4)&1)*8 + (lane&7))*80 + ((lane>>3)&1)*16);

    float run[2][8][4];
    float acc[2][8][4];
#pragma unroll
    for (int mt=0; mt<2; mt++)
#pragma unroll
        for (int nt=0; nt<8; nt++)
#pragma unroll
            for (int j=0; j<4; j++) run[mt][nt][j] = 0.f;

    float fz = 0.0f;

    // Prologue: one group = A band 0 + B chunks 0..2 (step 0)
    load_a(0, 0, sb, n, y0, tid);
    load_b(0, sb, k0, tid);
    load_b(1, sb, k0, tid);
    load_b(2, sb, k0, tid);
    cp_commit();

    for (int s = 0; s < 48; s++) {
        int cc = s/3;
        // issue next step's B chunks (+ next A band mid-chunk)
        if (s + 1 < 48) {
            load_b(3*(s+1),   sb, k0, tid);
            load_b(3*(s+1)+1, sb, k0, tid);
            load_b(3*(s+1)+2, sb, k0, tid);
        }
        if ((s % 3) == 1 && cc < 15) load_a(cc+1, (cc+1)&1, sb, n, y0, tid);
        cp_commit();
        cp_wait<1>();
        __syncthreads();

#pragma unroll
        for (int j = 0; j < 3; j++) {
            int c = 3*s + j;
            int tap = c % 9;
            int dy = tap/3, dx = tap - dy*3;
            uint32_t abase = sb + (cc&1)*A_BUF + aoff0 + (uint32_t)((dy*66 + dx)*80);
            uint32_t bbase = sb + B_BASE + (c%6)*B_SLOT + boff0;

#pragma unroll
            for (int ks = 0; ks < 2; ks++) {
                uint32_t kof = (uint32_t)(ks*32);
                uint32_t aH = abase + kof;
                uint32_t aL = aH + A_PLANE;
                uint32_t bH = bbase + kof;
                uint32_t bL = bH + B_PLANE;

                uint32_t ah[2][4], al[2][4], bh[8][2], bl[8][2];
                LDSM4(ah[0][0], ah[0][1], ah[0][2], ah[0][3], aH);
                LDSM4(ah[1][0], ah[1][1], ah[1][2], ah[1][3], aH + 1280);
                LDSM4(al[0][0], al[0][1], al[0][2], al[0][3], aL);
                LDSM4(al[1][0], al[1][1], al[1][2], al[1][3], aL + 1280);
                LDSM4(bh[0][0], bh[0][1], bh[1][0], bh[1][1], bH);
                LDSM4(bh[2][0], bh[2][1], bh[3][0], bh[3][1], bH + 1280);
                LDSM4(bh[4][0], bh[4][1], bh[5][0], bh[5][1], bH + 2560);
                LDSM4(bh[6][0], bh[6][1], bh[7][0], bh[7][1], bH + 3840);
                LDSM4(bl[0][0], bl[0][1], bl[1][0], bl[1][1], bL);
                LDSM4(bl[2][0], bl[2][1], bl[3][0], bl[3][1], bL + 1280);
                LDSM4(bl[4][0], bl[4][1], bl[5][0], bl[5][1], bL + 2560);
                LDSM4(bl[6][0], bl[6][1], bl[7][0], bl[7][1], bL + 3840);

                bool zc = (ks == 0) && (j == 0);   // window start (taps 0,3,6)
                // Pass 1: hh
                if (zc) {
#pragma unroll
                    for (int mt = 0; mt < 2; mt++)
#pragma unroll
                        for (int nt = 0; nt < 8; nt++)
                            MMA_F16_ZC(acc[mt][nt], ah[mt], bh[nt], fz);
                } else {
#pragma unroll
                    for (int mt = 0; mt < 2; mt++)
#pragma unroll
                        for (int nt = 0; nt < 8; nt++)
                            MMA_F16(acc[mt][nt], ah[mt], bh[nt]);
                }
                // Pass 2: hl
#pragma unroll
                for (int mt = 0; mt < 2; mt++)
#pragma unroll
                    for (int nt = 0; nt < 8; nt++)
                        MMA_F16(acc[mt][nt], ah[mt], bl[nt]);
                // Pass 3: lh
#pragma unroll
                for (int mt = 0; mt < 2; mt++)
#pragma unroll
                    for (int nt = 0; nt < 8; nt++)
                        MMA_F16(acc[mt][nt], al[mt], bh[nt]);
            }
        }
        // drain the 3-tap window (same boundaries as taps 2,5,8 before)
#pragma unroll
        for (int mt = 0; mt < 2; mt++)
#pragma unroll
            for (int nt = 0; nt < 8; nt++)
#pragma unroll
                for (int j = 0; j < 4; j++)
                    run[mt][nt][j] += acc[mt][nt][j];
        __syncthreads();
    }

    // ---- Fused epilogue ----
    float* hbuf = (float*)smem;                       // [128][HSTRIDE]
    float* w2   = (float*)(smem + 128*HSTRIDE*4);     // [54][128]

#pragma unroll
    for (int mt = 0; mt < 2; mt++) {
        int lr0 = wm*32 + mt*16 + g;
#pragma unroll
        for (int nt = 0; nt < 8; nt++) {
            int lch = wn*64 + nt*8 + t*2;
            int ch = k0 + lch;
            float b0 = bias[ch], b1 = bias[ch+1];
            hbuf[lr0*HSTRIDE + lch]     = fmaxf(fmaf(run[mt][nt][0], BUNSCALE, b0), 0.f);
            hbuf[lr0*HSTRIDE + lch + 1] = fmaxf(fmaf(run[mt][nt][1], BUNSCALE, b1), 0.f);
            hbuf[(lr0+8)*HSTRIDE + lch]     = fmaxf(fmaf(run[mt][nt][2], BUNSCALE, b0), 0.f);
            hbuf[(lr0+8)*HSTRIDE + lch + 1] = fmaxf(fmaf(run[mt][nt][3], BUNSCALE, b1), 0.f);
        }
    }
    for (int e = tid; e < 54*128; e += 256) {
        int o = e >> 7, cc = e & 127;
        w2[o*128 + cc] = (o < 18) ? sw[o*CIN + k0 + cc] : lw[(o-18)*CIN + k0 + cc];
    }
    __syncthreads();

    int px0 = tid & 63, og = tid >> 6;
#pragma unroll
    for (int half = 0; half < 2; half++) {
        int px = half*64 + px0;
        float hacc[14];
#pragma unroll
        for (int t14 = 0; t14 < 14; t14++) hacc[t14] = 0.f;
#pragma unroll 2
        for (int cc4 = 0; cc4 < 32; cc4++) {
            float4 hv = *(const float4*)&hbuf[px*HSTRIDE + cc4*4];
#pragma unroll
            for (int t14 = 0; t14 < 14; t14++) {
                int o = og + 4*t14;
                if (o < 54) {
                    float4 wv = *(const float4*)&w2[o*128 + cc4*4];
                    hacc[t14] = fmaf(wv.x, hv.x, hacc[t14]);
                    hacc[t14] = fmaf(wv.y, hv.y, hacc[t14]);
                    hacc[t14] = fmaf(wv.z, hv.z, hacc[t14]);
                    hacc[t14] = fmaf(wv.w, hv.w, hacc[t14]);
                }
            }
        }
        int pix = (p0 & 4095) + px;
#pragma unroll
        for (int t14 = 0; t14 < 14; t14++) {
            int o = og + 4*t14;
            if (o < 54)
                g_part[((size_t)((q*2+n)*56 + o))*4096 + pix] = hacc[t14];
        }
    }
}

// ---------------------------------------------------------------------------
// Anchor
// ---------------------------------------------------------------------------
__device__ __forceinline__ void anchor_calc(int y, int x, int k,
                                            float& o0, float& o1, float& o2, float& o3) {
    const double ratios[3] = {0.5, 1.0, 2.0};
    const double scales[3] = {8.0, 16.0, 32.0};
    int i = k/3, j = k%3;
    double h = 16.0*scales[j]*sqrt(ratios[i]);
    double w = 16.0*scales[j]*sqrt(1.0/ratios[i]);
    float b0 = (float)(8.0 - h*0.5);
    float b1 = (float)(8.0 - w*0.5);
    float b2 = (float)(8.0 + h*0.5);
    float b3 = (float)(8.0 + w*0.5);
    o0 = (float)((double)b0 + (double)(y*16));
    o1 = (float)((double)b1 + (double)(x*16));
    o2 = (float)((double)b2 + (double)(y*16));
    o3 = (float)((double)b3 + (double)(x*16));
}

__device__ __forceinline__ float load_dim(const void* p) {
    int iv = *(const int*)p;
    if (iv > 0 && iv < (1<<20)) return (float)iv;
    return *(const float*)p;
}

// ---------------------------------------------------------------------------
// Finalize. grid (128, 2): 32-pixel blocks.
// ---------------------------------------------------------------------------
__global__ __launch_bounds__(256) void finalize_kernel(const float* __restrict__ sb,
                                                       const float* __restrict__ lb,
                                                       const void* ihp, const void* iwp,
                                                       float* __restrict__ out) {
    __shared__ float s_o[54][32];
    int blk = blockIdx.x;
    int y = blk >> 1;
    int ph = (blk & 1) * 32;
    int n = blockIdx.y;
    int tid = threadIdx.x;

    for (int e=tid; e<1728; e+=256) {
        int px = e & 31, o = e >> 5;
        size_t base = (size_t)y*64 + ph + px;
        float s = 0.f;
#pragma unroll
        for (int q = 0; q < NQ; q++)
            s += g_part[((size_t)((q*2+n)*56 + o))*4096 + base];
        s += (o<18) ? sb[o] : lb[o-18];
        s_o[o][px] = s;
        int pix = y*64 + ph + px;
        if (o < 18)
            out[OFF_SCORES + ((size_t)n*ATOT + (size_t)pix*9 + (o>>1))*2 + (o&1)] = s;
        else {
            int c = o-18;
            out[OFF_LOCS + ((size_t)n*ATOT + (size_t)pix*9 + (c>>2))*4 + (c&3)] = s;
        }
    }
    __syncthreads();

    float img_h = load_dim(ihp), img_w = load_dim(iwp);

    for (int e=tid; e<288; e+=256) {
        int p2 = e & 31;
        int k  = e >> 5;
        float s0 = s_o[2*k][p2], s1 = s_o[2*k+1][p2];
        float m  = fmaxf(s0,s1);
        float e0 = expf(s0-m), e1 = expf(s1-m);
        float fg = e1/(e0+e1);

        float d0 = s_o[18+4*k+0][p2];
        float d1 = s_o[18+4*k+1][p2];
        float d2 = s_o[18+4*k+2][p2];
        float d3 = s_o[18+4*k+3][p2];

        int xcol = ph + p2;
        float a0,a1,a2,a3;
        anchor_calc(y, xcol, k, a0,a1,a2,a3);

        float ah = a2-a0, aw = a3-a1;
        float acy = a0 + 0.5f*ah, acx = a1 + 0.5f*aw;
        float cy = fmaf(d0, ah, acy);
        float cx = fmaf(d1, aw, acx);
        float h  = expf(d2)*ah;
        float w  = expf(d3)*aw;
        float r0 = fminf(fmaxf(cy-0.5f*h, 0.f), img_h);
        float r1 = fminf(fmaxf(cx-0.5f*w, 0.f), img_w);
        float r2 = fminf(fmaxf(cy+0.5f*h, 0.f), img_h);
        float r3 = fminf(fmaxf(cx+0.5f*w, 0.f), img_w);
        bool valid = (r2-r0 >= 16.f) && (r3-r1 >= 16.f);

        int aidx = (y*64 + xcol)*9 + k;
        int gi = n*ATOT + aidx;
        float sc = valid ? fg : -CUDART_INF_F;
        g_score[gi] = sc;
        g_roi[gi] = make_float4(r0,r1,r2,r3);
        uint32_t u = valid ? __float_as_uint(fg) : 0u;
        g_key32[gi] = u | ((uint32_t)(1 - n) << 30);
        g_val[gi] = gi;
        if (n == 0) {
            out[OFF_ANCHOR + (size_t)aidx*4 + 0] = a0;
            out[OFF_ANCHOR + (size_t)aidx*4 + 1] = a1;
            out[OFF_ANCHOR + (size_t)aidx*4 + 2] = a2;
            out[OFF_ANCHOR + (size_t)aidx*4 + 3] = a3;
        }
    }
}

// ---------------------------------------------------------------------------
// Gather top-6000 boxes + scores after sort
// ---------------------------------------------------------------------------
__global__ void gather_kernel() {
    int t = blockIdx.x*256 + threadIdx.x;
    if (t >= NB*NPRE) return;
    int n = t/NPRE, i = t%NPRE;
    int gi = g_val_out[n*ATOT + i];
    g_boxes[t] = g_roi[gi];
    g_boxsc[t] = g_score[gi];
}

// ---------------------------------------------------------------------------
// NMS bitmask (upper triangle jb >= ib only)
// ---------------------------------------------------------------------------
__global__ __launch_bounds__(64) void mask_kernel() {
    int n  = blockIdx.z;
    int jb = blockIdx.x;
    int ib = blockIdx.y;
    if (jb < ib) return;
    int t  = threadIdx.x;

    __shared__ float4 cb[64];
    int j = jb*64 + t;
    cb[t] = (j < NPRE) ? g_boxes[n*NPRE + j] : make_float4(0.f,0.f,0.f,0.f);
    __syncthreads();

    int i = ib*64 + t;
    if (i >= NPRE) return;
    float4 bi = g_boxes[n*NPRE + i];
    float areai = (bi.z-bi.x)*(bi.w-bi.y);

    unsigned long long word = 0ull;
    int jmax = min(64, NPRE - jb*64);
    for (int jj=0; jj<jmax; jj++) {
        float4 bj = cb[jj];
        float areaj = (bj.z-bj.x)*(bj.w-bj.y);
        float ih = fmaxf(fminf(bi.z,bj.z) - fmaxf(bi.x,bj.x), 0.f);
        float iw = fmaxf(fminf(bi.w,bj.w) - fmaxf(bi.y,bj.y), 0.f);
        float inter = ih*iw;
        float iou = inter/(areai + areaj - inter + 1e-9f);
        if (iou > NMS_T) word |= (1ull << jj);
    }
    g_mask[((size_t)n*NPRE + i)*MASKW + jb] = word;
}

// ---------------------------------------------------------------------------
// Greedy NMS scan + fused output
// ---------------------------------------------------------------------------
__global__ void scan_kernel(float* __restrict__ out) {
    int n = blockIdx.x;
    int lane = threadIdx.x;
    const unsigned FULL = 0xffffffffu;

    unsigned long long r0=0ull, r1=0ull, r2=0ull;
    int cnt = 0;
    const unsigned long long* mk = g_mask + (size_t)n*NPRE*MASKW;
    const float* sc = g_boxsc + n*NPRE;

    unsigned long long m0, m1;
    float s0, s1;
    {
        int i0 = lane, i1 = 32 + lane;
        m0 = mk[(size_t)i0*MASKW];
        m1 = mk[(size_t)i1*MASKW];
        s0 = sc[i0];
        s1 = sc[i1];
    }

    for (int ch=0; ch<MASKW; ch++) {
        unsigned long long nm0 = 0ull, nm1 = 0ull;
        float ns0 = -CUDART_INF_F, ns1 = -CUDART_INF_F;
        if (ch + 1 < MASKW) {
            int i0 = (ch+1)*64 + lane, i1 = i0 + 32;
            if (i0 < NPRE) { nm0 = mk[(size_t)i0*MASKW + ch + 1]; ns0 = sc[i0]; }
            if (i1 < NPRE) { nm1 = mk[(size_t)i1*MASKW + ch + 1]; ns1 = sc[i1]; }
        }

        unsigned inv0 = __ballot_sync(FULL, !isfinite(s0));
        unsigned inv1 = __ballot_sync(FULL, !isfinite(s1));
        unsigned long long W = (unsigned long long)inv0 | ((unsigned long long)inv1 << 32);

        int seg = ch >> 5, ln = ch & 31;
        unsigned long long rr = (seg==0) ? r0 : ((seg==1) ? r1 : r2);
        W |= __shfl_sync(FULL, rr, ln);

        unsigned long long keptb = 0ull;
        while (~W) {
            int p = __ffsll((long long)(~W)) - 1;
            keptb |= (1ull << p);
            if (lane == 0) g_kept[n*NPOST + cnt] = ch*64 + p;
            cnt++;
            if (cnt == NPOST) break;
            unsigned long long rw = __shfl_sync(FULL, (p<32) ? m0 : m1, p & 31);
            W |= rw;
        }
        if (cnt >= NPOST) break;

        unsigned long long kb = keptb;
        while (kb) {
            int p = __ffsll((long long)kb) - 1;
            kb &= kb - 1;
            size_t row = (size_t)(ch*64 + p)*MASKW;
            r0 |= mk[row + lane];
            r1 |= mk[row + 32 + lane];
            if (64 + lane < MASKW) r2 |= mk[row + 64 + lane];
        }

        m0 = nm0; m1 = nm1; s0 = ns0; s1 = ns1;
    }

    __threadfence_block();
    __syncwarp(FULL);
    for (int r = lane; r < NPOST; r += 32) {
        float4 b = make_float4(0.f,0.f,0.f,0.f);
        float vm = 0.f;
        if (r < cnt) {
            b = g_boxes[n*NPRE + g_kept[n*NPOST + r]];
            vm = 1.f;
        }
        size_t t = (size_t)n*NPOST + r;
        out[OFF_ROIS + t*4 + 0] = b.x;
        out[OFF_ROIS + t*4 + 1] = b.y;
        out[OFF_ROIS + t*4 + 2] = b.z;
        out[OFF_ROIS + t*4 + 3] = b.w;
        out[OFF_RIDX + t]  = (float)n;
        out[OFF_VMASK + t] = vm;
    }
}

// ---------------------------------------------------------------------------
// Launch
// ---------------------------------------------------------------------------
extern "C" void kernel_launch(void* const* d_in, const int* in_sizes, int n_in,
                              void* d_out, int out_size) {
    const float* x  = (const float*)d_in[0];
    const float* w  = (const float*)d_in[1];
    const float* b  = (const float*)d_in[2];
    const float* sw = (const float*)d_in[3];
    const float* sb = (const float*)d_in[4];
    const float* lw = (const float*)d_in[5];
    const float* lb = (const float*)d_in[6];
    float* out = (float*)d_out;

    cudaFuncSetAttribute(mma_conv_kernel,
                         cudaFuncAttributeMaxDynamicSharedMemorySize, SMEM_DYN);

    split_kernel<<<dim3(128, 16, 3), 256>>>(x, w);
    mma_conv_kernel<<<dim3(64, 4), 256, SMEM_DYN>>>(b, sw, lw);
    finalize_kernel<<<dim3(128, 2), 256>>>(sb, lb, d_in[7], d_in[8], out);

    void* tmp;
    uint32_t *ki, *ko;
    int *vi, *vo;
    cudaGetSymbolAddress(&tmp, g_cub_temp);
    cudaGetSymbolAddress((void**)&ki, g_key32);
    cudaGetSymbolAddress((void**)&ko, g_key32_out);
    cudaGetSymbolAddress((void**)&vi, g_val);
    cudaGetSymbolAddress((void**)&vo, g_val_out);

    {
        size_t tb = 0;
        cub::DeviceRadixSort::SortPairsDescending(nullptr, tb,
            ki, ko, vi, vo, NB*ATOT, 0, 31, (cudaStream_t)0);
        if (tb <= sizeof(g_cub_temp)) {
            cub::DeviceRadixSort::SortPairsDescending(tmp, tb,
                ki, ko, vi, vo, NB*ATOT, 0, 31, (cudaStream_t)0);
        }
    }

    gather_kernel<<<(NB*NPRE + 255)/256, 256>>>();
    mask_kernel<<<dim3(MASKW, MASKW, NB), 64>>>();
    scan_kernel<<<NB, 32>>>(out);
}